// round 7
// baseline (speedup 1.0000x reference)
#include <cuda_runtime.h>
#include <math.h>

// Problem constants
#define BQ 4
#define LQ 512
#define HQ 1024
#define MQ 128
#define EQ 64
#define NHQ 16
#define RQ 1024
#define DQ 768
#define BLKQ 64
#define CQ 97
#define NKB 12           // D / BLK
#define NP (BQ * RQ)     // 4096 pairs

// -------- scratch (static device globals: allocation-guard safe) ----------
__device__ float g_ent_emb[BQ * EQ * HQ];          // 1 MB
__device__ int   g_cnt[BQ * EQ];
__device__ int   g_list[BQ * EQ * MQ];
__device__ float g_ent_attn[BQ * EQ * NHQ * LQ];   // 8 MB
__device__ float g_ht[NP * LQ];                    // 8 MB
__device__ float g_rel[NP * HQ];                   // 16 MB
__device__ float g_hv[NP * DQ];                    // 12 MB
__device__ float g_tv[NP * DQ];                    // 12 MB
__device__ float g_part[NKB * NP * CQ];            // 19 MB split-K partials

// ---------------------------------------------------------------------------
// K0: per (b,e) mention index lists
// ---------------------------------------------------------------------------
__global__ void k_build(const int* __restrict__ labels) {
    int b = blockIdx.x, e = threadIdx.x;       // grid: B, block: E
    int c = 0;
    int* lst = g_list + (b * EQ + e) * MQ;
    for (int m = 0; m < MQ; m++)
        if (labels[b * MQ + m] == e) lst[c++] = m;
    g_cnt[b * EQ + e] = c;
}

// ---------------------------------------------------------------------------
// K1: segment logsumexp over mentions -> ent_emb [B,E,H]
// ---------------------------------------------------------------------------
__global__ void k_ent_emb(const float* __restrict__ ent_lhs) {
    int be = blockIdx.x;                 // grid: B*E, block: 256
    int b = be / EQ;
    __shared__ int s_list[MQ];
    int cnt = g_cnt[be];
    for (int i = threadIdx.x; i < cnt; i += 256) s_list[i] = g_list[be * MQ + i];
    __syncthreads();
    const float* base = ent_lhs + (size_t)b * MQ * HQ;
    for (int h = threadIdx.x; h < HQ; h += 256) {
        float o = 0.f;
        if (cnt > 0) {
            float mx = -3.4e38f;
            for (int i = 0; i < cnt; i++) mx = fmaxf(mx, base[s_list[i] * HQ + h]);
            float s = 0.f;
            for (int i = 0; i < cnt; i++) s += expf(base[s_list[i] * HQ + h] - mx);
            o = mx + logf(s);
        }
        g_ent_emb[be * HQ + h] = o;
    }
}

// ---------------------------------------------------------------------------
// K2: mean mention attention -> ent_attn [B,E,NH,L]
// ---------------------------------------------------------------------------
__global__ void k_ent_attn(const float* __restrict__ attn) {
    int be = blockIdx.y, nh = blockIdx.x;   // grid: (NH, B*E), block: 128
    int b = be / EQ;
    int cnt = g_cnt[be];
    __shared__ int s_list[MQ];
    for (int i = threadIdx.x; i < cnt; i += 128) s_list[i] = g_list[be * MQ + i];
    __syncthreads();
    float inv = (cnt > 0) ? 1.f / (float)cnt : 0.f;
    const float* abase = attn + ((size_t)(b * NHQ + nh)) * MQ * LQ;
    float* obase = g_ent_attn + ((size_t)(be * NHQ + nh)) * LQ;
    for (int l = threadIdx.x; l < LQ; l += 128) {
        float s = 0.f;
        for (int i = 0; i < cnt; i++) s += abase[s_list[i] * LQ + l];
        obase[l] = s * inv;
    }
}

// ---------------------------------------------------------------------------
// K3: pair attention product, mean over heads, normalize -> g_ht [NP,L]
// ---------------------------------------------------------------------------
__global__ void k_ht(const int* __restrict__ hts) {
    int n = blockIdx.x;                 // grid: NP, block: 128
    int b = n / RQ;
    int he = hts[n * 2 + 0];
    int te = hts[n * 2 + 1];
    const float* ha = g_ent_attn + ((size_t)(b * EQ + he)) * NHQ * LQ;
    const float* ta = g_ent_attn + ((size_t)(b * EQ + te)) * NHQ * LQ;
    float v[4];
    float loc = 0.f;
#pragma unroll
    for (int rep = 0; rep < 4; rep++) {
        int l = threadIdx.x + rep * 128;
        float acc = 0.f;
#pragma unroll
        for (int nh = 0; nh < NHQ; nh++) acc += ha[nh * LQ + l] * ta[nh * LQ + l];
        v[rep] = acc * (1.0f / NHQ);
        loc += v[rep];
    }
    __shared__ float red[128];
    red[threadIdx.x] = loc;
    __syncthreads();
    for (int s = 64; s > 0; s >>= 1) {
        if (threadIdx.x < s) red[threadIdx.x] += red[threadIdx.x + s];
        __syncthreads();
    }
    float inv = 1.f / (red[0] + 1e-5f);
#pragma unroll
    for (int rep = 0; rep < 4; rep++)
        g_ht[(size_t)n * LQ + threadIdx.x + rep * 128] = v[rep] * inv;
}

// ---------------------------------------------------------------------------
// K4: rel = ht_attn @ seq_lhs    (batched 1024x1024x512)
// classic 128x128x8 tile, 256 threads, 8x8 microtile
// ---------------------------------------------------------------------------
__global__ __launch_bounds__(256) void gemm_rel(const float* __restrict__ seq) {
    int b = blockIdx.z;
    int n0 = blockIdx.x * 128;   // column in H
    int r0 = blockIdx.y * 128;   // row within batch
    __shared__ float As[8][128];
    __shared__ float Bsh[8][128];
    float acc[8][8];
#pragma unroll
    for (int i = 0; i < 8; i++)
#pragma unroll
        for (int j = 0; j < 8; j++) acc[i][j] = 0.f;

    int tid = threadIdx.x;
    int arow = tid >> 1, akc = (tid & 1) * 4;
    int brow = tid >> 5, bcc = (tid & 31) * 4;
    int rm = (tid >> 4) * 8, rn = (tid & 15) * 8;
    const float* Abase = g_ht + (size_t)(b * RQ + r0) * LQ;
    const float* Bbase = seq + (size_t)b * LQ * HQ + n0;

    for (int k0 = 0; k0 < LQ; k0 += 8) {
        float4 av = *(const float4*)(Abase + (size_t)arow * LQ + k0 + akc);
        float4 bv = *(const float4*)(Bbase + (size_t)(k0 + brow) * HQ + bcc);
        __syncthreads();
        As[akc + 0][arow] = av.x; As[akc + 1][arow] = av.y;
        As[akc + 2][arow] = av.z; As[akc + 3][arow] = av.w;
        *(float4*)&Bsh[brow][bcc] = bv;
        __syncthreads();
#pragma unroll
        for (int kk = 0; kk < 8; kk++) {
            float a[8], bfr[8];
            *(float4*)&a[0] = *(const float4*)&As[kk][rm];
            *(float4*)&a[4] = *(const float4*)&As[kk][rm + 4];
            *(float4*)&bfr[0] = *(const float4*)&Bsh[kk][rn];
            *(float4*)&bfr[4] = *(const float4*)&Bsh[kk][rn + 4];
#pragma unroll
            for (int i = 0; i < 8; i++)
#pragma unroll
                for (int j = 0; j < 8; j++) acc[i][j] += a[i] * bfr[j];
        }
    }
    float* Cb = g_rel + (size_t)(b * RQ + r0) * HQ + n0;
#pragma unroll
    for (int i = 0; i < 8; i++)
#pragma unroll
        for (int j = 0; j < 8; j++)
            Cb[(size_t)(rm + i) * HQ + rn + j] = acc[i][j];
}

// ---------------------------------------------------------------------------
// K5: hv/tv = tanh([gathered_ent_emb | rel] @ W + bias)
// A is virtual: k<1024 -> ent_emb gather, else rel. z=0: head/Wh, z=1: tail/Wt
// ---------------------------------------------------------------------------
__global__ __launch_bounds__(256) void gemm_extract(
    const int* __restrict__ hts,
    const float* __restrict__ Wh, const float* __restrict__ bh,
    const float* __restrict__ Wt, const float* __restrict__ bt) {
    int z = blockIdx.z;
    int n0 = blockIdx.x * 128;    // column in D
    int p0 = blockIdx.y * 128;    // global pair row
    const float* W = z ? Wt : Wh;
    const float* bias = z ? bt : bh;
    float* C = z ? g_tv : g_hv;

    __shared__ float As[8][128];
    __shared__ float Bsh[8][128];
    __shared__ int s_eoff[128];
    int tid = threadIdx.x;
    if (tid < 128) {
        int n = p0 + tid;
        int b = n / RQ;
        int e = hts[n * 2 + z];
        s_eoff[tid] = (b * EQ + e) * HQ;
    }
    __syncthreads();

    float acc[8][8];
#pragma unroll
    for (int i = 0; i < 8; i++)
#pragma unroll
        for (int j = 0; j < 8; j++) acc[i][j] = 0.f;

    int arow = tid >> 1, akc = (tid & 1) * 4;
    int brow = tid >> 5, bcc = (tid & 31) * 4;
    int rm = (tid >> 4) * 8, rn = (tid & 15) * 8;

    for (int k0 = 0; k0 < 2 * HQ; k0 += 8) {
        const float* asrc = (k0 < HQ)
            ? (g_ent_emb + s_eoff[arow] + k0 + akc)
            : (g_rel + (size_t)(p0 + arow) * HQ + (k0 - HQ) + akc);
        float4 av = *(const float4*)asrc;
        float4 bv = *(const float4*)(W + (size_t)(k0 + brow) * DQ + n0 + bcc);
        __syncthreads();
        As[akc + 0][arow] = av.x; As[akc + 1][arow] = av.y;
        As[akc + 2][arow] = av.z; As[akc + 3][arow] = av.w;
        *(float4*)&Bsh[brow][bcc] = bv;
        __syncthreads();
#pragma unroll
        for (int kk = 0; kk < 8; kk++) {
            float a[8], bfr[8];
            *(float4*)&a[0] = *(const float4*)&As[kk][rm];
            *(float4*)&a[4] = *(const float4*)&As[kk][rm + 4];
            *(float4*)&bfr[0] = *(const float4*)&Bsh[kk][rn];
            *(float4*)&bfr[4] = *(const float4*)&Bsh[kk][rn + 4];
#pragma unroll
            for (int i = 0; i < 8; i++)
#pragma unroll
                for (int j = 0; j < 8; j++) acc[i][j] += a[i] * bfr[j];
        }
    }
#pragma unroll
    for (int i = 0; i < 8; i++) {
        int row = p0 + rm + i;
#pragma unroll
        for (int j = 0; j < 8; j++) {
            int col = n0 + rn + j;
            C[(size_t)row * DQ + col] = tanhf(acc[i][j] + bias[col]);
        }
    }
}

// ---------------------------------------------------------------------------
// K6: final block-bilinear GEMM.
// out[n,c] = sum_{k,i,j} hv[n,k*64+i] * tv[n,k*64+j] * Wb[k*4096+i*64+j, c]
// A synthesized in registers. Split-K over k (12 blocks) into g_part.
// grid: (32 M-blocks, 12 k-blocks), 256 threads, BM=128, BN=128 (C padded).
// dynamic smem: tvT[64][132] + hvT[64][132] + Ws[64][128] = 100352 B
// ---------------------------------------------------------------------------
extern __shared__ float s_fin[];
__global__ __launch_bounds__(256) void gemm_final(const float* __restrict__ Wb) {
    int p0 = blockIdx.x * 128;
    int kb = blockIdx.y;
    float* tvT = s_fin;                  // [64][132] j-major
    float* hvT = s_fin + 64 * 132;       // [64][132] i-major
    float* Ws  = s_fin + 2 * 64 * 132;   // [64][128]
    int tid = threadIdx.x;

    // load hv/tv tiles (once per block: kb fixed), transposed
#pragma unroll
    for (int it = 0; it < 8; it++) {
        int idx = tid + it * 256;        // 0..2047 float4 slots
        int row = idx >> 4;
        int c4 = (idx & 15) * 4;
        const float* hp = g_hv + (size_t)(p0 + row) * DQ + kb * 64 + c4;
        const float* tp = g_tv + (size_t)(p0 + row) * DQ + kb * 64 + c4;
        float4 h4 = *(const float4*)hp;
        float4 t4 = *(const float4*)tp;
        hvT[(c4 + 0) * 132 + row] = h4.x; hvT[(c4 + 1) * 132 + row] = h4.y;
        hvT[(c4 + 2) * 132 + row] = h4.z; hvT[(c4 + 3) * 132 + row] = h4.w;
        tvT[(c4 + 0) * 132 + row] = t4.x; tvT[(c4 + 1) * 132 + row] = t4.y;
        tvT[(c4 + 2) * 132 + row] = t4.z; tvT[(c4 + 3) * 132 + row] = t4.w;
    }

    float acc[8][8];
#pragma unroll
    for (int i = 0; i < 8; i++)
#pragma unroll
        for (int j = 0; j < 8; j++) acc[i][j] = 0.f;

    int rm = (tid >> 4) * 8, rn = (tid & 15) * 8;
    const float* Wbase = Wb + (size_t)kb * 4096 * CQ;

    for (int i = 0; i < 64; i++) {
        __syncthreads();   // previous stage compute done (and tile loads on i==0)
        // stream Wb slab for (kb, i): rows j=0..63, padded cols 0..127
        for (int t = tid; t < 64 * 128; t += 256) {
            int j = t >> 7, c = t & 127;
            Ws[t] = (c < CQ) ? Wbase[(size_t)(i * 64 + j) * CQ + c] : 0.f;
        }
        __syncthreads();
        float hvi[8];
        *(float4*)&hvi[0] = *(const float4*)&hvT[i * 132 + rm];
        *(float4*)&hvi[4] = *(const float4*)&hvT[i * 132 + rm + 4];
#pragma unroll 4
        for (int j = 0; j < 64; j++) {
            float tvj[8], wbf[8];
            *(float4*)&tvj[0] = *(const float4*)&tvT[j * 132 + rm];
            *(float4*)&tvj[4] = *(const float4*)&tvT[j * 132 + rm + 4];
            *(float4*)&wbf[0] = *(const float4*)&Ws[j * 128 + rn];
            *(float4*)&wbf[4] = *(const float4*)&Ws[j * 128 + rn + 4];
#pragma unroll
            for (int ii = 0; ii < 8; ii++) {
                float av = hvi[ii] * tvj[ii];
#pragma unroll
                for (int jj = 0; jj < 8; jj++) acc[ii][jj] += av * wbf[jj];
            }
        }
    }

    float* P = g_part + (size_t)kb * NP * CQ;
#pragma unroll
    for (int ii = 0; ii < 8; ii++) {
        int row = p0 + rm + ii;
#pragma unroll
        for (int jj = 0; jj < 8; jj++) {
            int c = rn + jj;
            if (c < CQ) P[(size_t)row * CQ + c] = acc[ii][jj];
        }
    }
}

// ---------------------------------------------------------------------------
// K7: deterministic split-K reduction + bias
// ---------------------------------------------------------------------------
__global__ void k_reduce(const float* __restrict__ bbias, float* __restrict__ out) {
    int idx = blockIdx.x * 256 + threadIdx.x;
    if (idx < NP * CQ) {
        int c = idx % CQ;
        float s = bbias[c];
#pragma unroll
        for (int z = 0; z < NKB; z++) s += g_part[(size_t)z * NP * CQ + idx];
        out[idx] = s;
    }
}

// ---------------------------------------------------------------------------
extern "C" void kernel_launch(void* const* d_in, const int* in_sizes, int n_in,
                              void* d_out, int out_size) {
    const float* seq     = (const float*)d_in[0];   // [B,L,H]
    const float* ent_lhs = (const float*)d_in[1];   // [B,M,H]
    const float* attn    = (const float*)d_in[2];   // [B,NH,M,L]
    const int*   labels  = (const int*)d_in[3];     // [B,M]
    const int*   hts     = (const int*)d_in[4];     // [B,R,2]
    const float* Wh      = (const float*)d_in[5];   // [2H,D]
    const float* bh      = (const float*)d_in[6];   // [D]
    const float* Wt      = (const float*)d_in[7];
    const float* bt      = (const float*)d_in[8];
    const float* Wb      = (const float*)d_in[9];   // [D*BLK,C]
    const float* bbias   = (const float*)d_in[10];  // [C]
    float* out = (float*)d_out;

    const int FIN_SMEM = (2 * 64 * 132 + 64 * 128) * 4;  // 100352 bytes
    cudaFuncSetAttribute(gemm_final, cudaFuncAttributeMaxDynamicSharedMemorySize, FIN_SMEM);

    k_build<<<BQ, EQ>>>(labels);
    k_ent_emb<<<BQ * EQ, 256>>>(ent_lhs);
    k_ent_attn<<<dim3(NHQ, BQ * EQ), 128>>>(attn);
    k_ht<<<NP, 128>>>(hts);
    gemm_rel<<<dim3(HQ / 128, RQ / 128, BQ), 256>>>(seq);
    gemm_extract<<<dim3(DQ / 128, NP / 128, 2), 256>>>(hts, Wh, bh, Wt, bt);
    gemm_final<<<dim3(NP / 128, NKB), 256, FIN_SMEM>>>(Wb);
    k_reduce<<<(NP * CQ + 255) / 256, 256>>>(bbias, out);
}

// round 8
// speedup vs baseline: 1.1309x; 1.1309x over previous
#include <cuda_runtime.h>
#include <math.h>

// Problem constants
#define BQ 4
#define LQ 512
#define HQ 1024
#define MQ 128
#define EQ 64
#define NHQ 16
#define RQ 1024
#define DQ 768
#define BLKQ 64
#define CQ 97
#define NKB 12           // D / BLK
#define NP (BQ * RQ)     // 4096 pairs

// -------- scratch (static device globals: allocation-guard safe) ----------
__device__ float g_ent_emb[BQ * EQ * HQ];          // 1 MB
__device__ int   g_cnt[BQ * EQ];
__device__ int   g_list[BQ * EQ * MQ];
__device__ float g_ent_attn[BQ * EQ * NHQ * LQ];   // 8 MB
__device__ float g_ht[NP * LQ];                    // 8 MB
__device__ float g_rel[NP * HQ];                   // 16 MB
__device__ float g_hv[NP * DQ];                    // 12 MB
__device__ float g_tv[NP * DQ];                    // 12 MB
__device__ float g_part[NKB * NP * CQ];            // 19 MB split-K partials

// -------- packed f32x2 helpers (sm_100+: FFMA2 only reachable via PTX) ----
typedef unsigned long long u64t;

__device__ __forceinline__ u64t pack2b(float v) {           // {v, v}
    u64t r; asm("mov.b64 %0, {%1, %1};" : "=l"(r) : "f"(v)); return r;
}
__device__ __forceinline__ u64t mul2(u64t a, u64t b) {
    u64t r; asm("mul.rn.f32x2 %0, %1, %2;" : "=l"(r) : "l"(a), "l"(b)); return r;
}
__device__ __forceinline__ void fma2(u64t& d, u64t a, u64t b) {
    asm("fma.rn.f32x2 %0, %1, %2, %0;" : "+l"(d) : "l"(a), "l"(b));
}
__device__ __forceinline__ float2 unpack2(u64t v) {
    float2 r; asm("mov.b64 {%0, %1}, %2;" : "=f"(r.x), "=f"(r.y) : "l"(v)); return r;
}

// ---------------------------------------------------------------------------
// K0: per (b,e) mention index lists
// ---------------------------------------------------------------------------
__global__ void k_build(const int* __restrict__ labels) {
    int b = blockIdx.x, e = threadIdx.x;       // grid: B, block: E
    int c = 0;
    int* lst = g_list + (b * EQ + e) * MQ;
    for (int m = 0; m < MQ; m++)
        if (labels[b * MQ + m] == e) lst[c++] = m;
    g_cnt[b * EQ + e] = c;
}

// ---------------------------------------------------------------------------
// K1: segment logsumexp over mentions -> ent_emb [B,E,H]
// ---------------------------------------------------------------------------
__global__ void k_ent_emb(const float* __restrict__ ent_lhs) {
    int be = blockIdx.x;                 // grid: B*E, block: 256
    int b = be / EQ;
    __shared__ int s_list[MQ];
    int cnt = g_cnt[be];
    for (int i = threadIdx.x; i < cnt; i += 256) s_list[i] = g_list[be * MQ + i];
    __syncthreads();
    const float* base = ent_lhs + (size_t)b * MQ * HQ;
    for (int h = threadIdx.x; h < HQ; h += 256) {
        float o = 0.f;
        if (cnt > 0) {
            float mx = -3.4e38f;
            for (int i = 0; i < cnt; i++) mx = fmaxf(mx, base[s_list[i] * HQ + h]);
            float s = 0.f;
            for (int i = 0; i < cnt; i++) s += expf(base[s_list[i] * HQ + h] - mx);
            o = mx + logf(s);
        }
        g_ent_emb[be * HQ + h] = o;
    }
}

// ---------------------------------------------------------------------------
// K2: mean mention attention -> ent_attn [B,E,NH,L]
// ---------------------------------------------------------------------------
__global__ void k_ent_attn(const float* __restrict__ attn) {
    int be = blockIdx.y, nh = blockIdx.x;   // grid: (NH, B*E), block: 128
    int b = be / EQ;
    int cnt = g_cnt[be];
    __shared__ int s_list[MQ];
    for (int i = threadIdx.x; i < cnt; i += 128) s_list[i] = g_list[be * MQ + i];
    __syncthreads();
    float inv = (cnt > 0) ? 1.f / (float)cnt : 0.f;
    const float* abase = attn + ((size_t)(b * NHQ + nh)) * MQ * LQ;
    float* obase = g_ent_attn + ((size_t)(be * NHQ + nh)) * LQ;
    for (int l = threadIdx.x; l < LQ; l += 128) {
        float s = 0.f;
        for (int i = 0; i < cnt; i++) s += abase[s_list[i] * LQ + l];
        obase[l] = s * inv;
    }
}

// ---------------------------------------------------------------------------
// K3: pair attention product, mean over heads, normalize -> g_ht [NP,L]
// ---------------------------------------------------------------------------
__global__ void k_ht(const int* __restrict__ hts) {
    int n = blockIdx.x;                 // grid: NP, block: 128
    int b = n / RQ;
    int he = hts[n * 2 + 0];
    int te = hts[n * 2 + 1];
    const float* ha = g_ent_attn + ((size_t)(b * EQ + he)) * NHQ * LQ;
    const float* ta = g_ent_attn + ((size_t)(b * EQ + te)) * NHQ * LQ;
    float v[4];
    float loc = 0.f;
#pragma unroll
    for (int rep = 0; rep < 4; rep++) {
        int l = threadIdx.x + rep * 128;
        float acc = 0.f;
#pragma unroll
        for (int nh = 0; nh < NHQ; nh++) acc += ha[nh * LQ + l] * ta[nh * LQ + l];
        v[rep] = acc * (1.0f / NHQ);
        loc += v[rep];
    }
    __shared__ float red[128];
    red[threadIdx.x] = loc;
    __syncthreads();
    for (int s = 64; s > 0; s >>= 1) {
        if (threadIdx.x < s) red[threadIdx.x] += red[threadIdx.x + s];
        __syncthreads();
    }
    float inv = 1.f / (red[0] + 1e-5f);
#pragma unroll
    for (int rep = 0; rep < 4; rep++)
        g_ht[(size_t)n * LQ + threadIdx.x + rep * 128] = v[rep] * inv;
}

// ---------------------------------------------------------------------------
// K4: rel = ht_attn @ seq_lhs    (batched 1024x1024x512)
// 128x128x16 tile, 256 threads, 8x8 microtile, f32x2 FMA (pack along j)
// ---------------------------------------------------------------------------
__global__ __launch_bounds__(256) void gemm_rel(const float* __restrict__ seq) {
    int b = blockIdx.z;
    int n0 = blockIdx.x * 128;   // column in H
    int r0 = blockIdx.y * 128;   // row within batch
    __shared__ float As[16][128];
    __shared__ float Bsh[16][128];
    u64t acc2[8][4];
#pragma unroll
    for (int i = 0; i < 8; i++)
#pragma unroll
        for (int j = 0; j < 4; j++) acc2[i][j] = 0ULL;

    int tid = threadIdx.x;
    int arow = tid >> 1, akc = (tid & 1) * 8;
    int brow = tid >> 4, bcc = (tid & 15) * 8;
    int rm = (tid >> 4) * 8, rn = (tid & 15) * 8;
    const float* Abase = g_ht + (size_t)(b * RQ + r0) * LQ;
    const float* Bbase = seq + (size_t)b * LQ * HQ + n0;

    for (int k0 = 0; k0 < LQ; k0 += 16) {
        float4 a0 = *(const float4*)(Abase + (size_t)arow * LQ + k0 + akc);
        float4 a1 = *(const float4*)(Abase + (size_t)arow * LQ + k0 + akc + 4);
        float4 b0 = *(const float4*)(Bbase + (size_t)(k0 + brow) * HQ + bcc);
        float4 b1 = *(const float4*)(Bbase + (size_t)(k0 + brow) * HQ + bcc + 4);
        __syncthreads();
        As[akc + 0][arow] = a0.x; As[akc + 1][arow] = a0.y;
        As[akc + 2][arow] = a0.z; As[akc + 3][arow] = a0.w;
        As[akc + 4][arow] = a1.x; As[akc + 5][arow] = a1.y;
        As[akc + 6][arow] = a1.z; As[akc + 7][arow] = a1.w;
        *(float4*)&Bsh[brow][bcc] = b0;
        *(float4*)&Bsh[brow][bcc + 4] = b1;
        __syncthreads();
#pragma unroll
        for (int kk = 0; kk < 16; kk++) {
            float a[8];
            *(float4*)&a[0] = *(const float4*)&As[kk][rm];
            *(float4*)&a[4] = *(const float4*)&As[kk][rm + 4];
            ulonglong2 bu0 = *(const ulonglong2*)&Bsh[kk][rn];
            ulonglong2 bu1 = *(const ulonglong2*)&Bsh[kk][rn + 4];
            u64t b2[4] = {bu0.x, bu0.y, bu1.x, bu1.y};
#pragma unroll
            for (int i = 0; i < 8; i++) {
                u64t a2 = pack2b(a[i]);
#pragma unroll
                for (int j = 0; j < 4; j++) fma2(acc2[i][j], a2, b2[j]);
            }
        }
    }
    float* Cb = g_rel + (size_t)(b * RQ + r0) * HQ + n0;
#pragma unroll
    for (int i = 0; i < 8; i++)
#pragma unroll
        for (int j = 0; j < 4; j++) {
            float2 v = unpack2(acc2[i][j]);
            *(float2*)&Cb[(size_t)(rm + i) * HQ + rn + 2 * j] = v;
        }
}

// ---------------------------------------------------------------------------
// K5: hv/tv = tanh([gathered_ent_emb | rel] @ W + bias)
// A virtual: k<1024 -> ent_emb gather, else rel. z=0: head/Wh, z=1: tail/Wt
// 128x128x16 tile, f32x2 FMA (pack along j)
// ---------------------------------------------------------------------------
__global__ __launch_bounds__(256) void gemm_extract(
    const int* __restrict__ hts,
    const float* __restrict__ Wh, const float* __restrict__ bh,
    const float* __restrict__ Wt, const float* __restrict__ bt) {
    int z = blockIdx.z;
    int n0 = blockIdx.x * 128;    // column in D
    int p0 = blockIdx.y * 128;    // global pair row
    const float* W = z ? Wt : Wh;
    const float* bias = z ? bt : bh;
    float* C = z ? g_tv : g_hv;

    __shared__ float As[16][128];
    __shared__ float Bsh[16][128];
    __shared__ int s_eoff[128];
    int tid = threadIdx.x;
    if (tid < 128) {
        int n = p0 + tid;
        int b = n / RQ;
        int e = hts[n * 2 + z];
        s_eoff[tid] = (b * EQ + e) * HQ;
    }
    __syncthreads();

    u64t acc2[8][4];
#pragma unroll
    for (int i = 0; i < 8; i++)
#pragma unroll
        for (int j = 0; j < 4; j++) acc2[i][j] = 0ULL;

    int arow = tid >> 1, akc = (tid & 1) * 8;
    int brow = tid >> 4, bcc = (tid & 15) * 8;
    int rm = (tid >> 4) * 8, rn = (tid & 15) * 8;

    for (int k0 = 0; k0 < 2 * HQ; k0 += 16) {
        const float* asrc = (k0 < HQ)
            ? (g_ent_emb + s_eoff[arow] + k0 + akc)
            : (g_rel + (size_t)(p0 + arow) * HQ + (k0 - HQ) + akc);
        float4 a0 = *(const float4*)asrc;
        float4 a1 = *(const float4*)(asrc + 4);
        float4 b0 = *(const float4*)(W + (size_t)(k0 + brow) * DQ + n0 + bcc);
        float4 b1 = *(const float4*)(W + (size_t)(k0 + brow) * DQ + n0 + bcc + 4);
        __syncthreads();
        As[akc + 0][arow] = a0.x; As[akc + 1][arow] = a0.y;
        As[akc + 2][arow] = a0.z; As[akc + 3][arow] = a0.w;
        As[akc + 4][arow] = a1.x; As[akc + 5][arow] = a1.y;
        As[akc + 6][arow] = a1.z; As[akc + 7][arow] = a1.w;
        *(float4*)&Bsh[brow][bcc] = b0;
        *(float4*)&Bsh[brow][bcc + 4] = b1;
        __syncthreads();
#pragma unroll
        for (int kk = 0; kk < 16; kk++) {
            float a[8];
            *(float4*)&a[0] = *(const float4*)&As[kk][rm];
            *(float4*)&a[4] = *(const float4*)&As[kk][rm + 4];
            ulonglong2 bu0 = *(const ulonglong2*)&Bsh[kk][rn];
            ulonglong2 bu1 = *(const ulonglong2*)&Bsh[kk][rn + 4];
            u64t b2[4] = {bu0.x, bu0.y, bu1.x, bu1.y};
#pragma unroll
            for (int i = 0; i < 8; i++) {
                u64t a2 = pack2b(a[i]);
#pragma unroll
                for (int j = 0; j < 4; j++) fma2(acc2[i][j], a2, b2[j]);
            }
        }
    }
#pragma unroll
    for (int i = 0; i < 8; i++) {
        int row = p0 + rm + i;
#pragma unroll
        for (int j = 0; j < 4; j++) {
            float2 v = unpack2(acc2[i][j]);
            int col = n0 + rn + 2 * j;
            C[(size_t)row * DQ + col]     = tanhf(v.x + bias[col]);
            C[(size_t)row * DQ + col + 1] = tanhf(v.y + bias[col + 1]);
        }
    }
}

// ---------------------------------------------------------------------------
// K6: final block-bilinear GEMM, f32x2 FMA (pack along rows ii).
// out[n,c] = sum_{k,i,j} hv[n,k*64+i] * tv[n,k*64+j] * Wb[k*4096+i*64+j, c]
// A synthesized in registers (av = hv*tv via mul.f32x2 on natural row pairs).
// Split-K over k (12 blocks) into g_part.
// grid: (32 M-blocks, 12 k-blocks), 256 threads, BM=128, BN=128 (C padded).
// dynamic smem: tvT[64][132] + hvT[64][132] + Ws[64][128] = 100352 B
// ---------------------------------------------------------------------------
extern __shared__ float s_fin[];
__global__ __launch_bounds__(256) void gemm_final(const float* __restrict__ Wb) {
    int p0 = blockIdx.x * 128;
    int kb = blockIdx.y;
    float* tvT = s_fin;                  // [64][132] j-major
    float* hvT = s_fin + 64 * 132;       // [64][132] i-major
    float* Ws  = s_fin + 2 * 64 * 132;   // [64][128]
    int tid = threadIdx.x;

    // load hv/tv tiles (once per block: kb fixed), transposed
#pragma unroll
    for (int it = 0; it < 8; it++) {
        int idx = tid + it * 256;        // 0..2047 float4 slots
        int row = idx >> 4;
        int c4 = (idx & 15) * 4;
        const float* hp = g_hv + (size_t)(p0 + row) * DQ + kb * 64 + c4;
        const float* tp = g_tv + (size_t)(p0 + row) * DQ + kb * 64 + c4;
        float4 h4 = *(const float4*)hp;
        float4 t4 = *(const float4*)tp;
        hvT[(c4 + 0) * 132 + row] = h4.x; hvT[(c4 + 1) * 132 + row] = h4.y;
        hvT[(c4 + 2) * 132 + row] = h4.z; hvT[(c4 + 3) * 132 + row] = h4.w;
        tvT[(c4 + 0) * 132 + row] = t4.x; tvT[(c4 + 1) * 132 + row] = t4.y;
        tvT[(c4 + 2) * 132 + row] = t4.z; tvT[(c4 + 3) * 132 + row] = t4.w;
    }

    u64t acc2[4][8];                     // [row-pair ii2][col jj]
#pragma unroll
    for (int i = 0; i < 4; i++)
#pragma unroll
        for (int j = 0; j < 8; j++) acc2[i][j] = 0ULL;

    int rm = (tid >> 4) * 8, rn = (tid & 15) * 8;
    const float* Wbase = Wb + (size_t)kb * 4096 * CQ;

    for (int i = 0; i < 64; i++) {
        __syncthreads();   // previous stage compute done (and tile loads on i==0)
        // stream Wb slab for (kb, i): rows j=0..63, padded cols 0..127
        for (int t = tid; t < 64 * 128; t += 256) {
            int j = t >> 7, c = t & 127;
            Ws[t] = (c < CQ) ? Wbase[(size_t)(i * 64 + j) * CQ + c] : 0.f;
        }
        __syncthreads();
        ulonglong2 h0 = *(const ulonglong2*)&hvT[i * 132 + rm];
        ulonglong2 h1 = *(const ulonglong2*)&hvT[i * 132 + rm + 4];
        u64t hv2[4] = {h0.x, h0.y, h1.x, h1.y};
#pragma unroll 4
        for (int j = 0; j < 64; j++) {
            ulonglong2 t0 = *(const ulonglong2*)&tvT[j * 132 + rm];
            ulonglong2 t1 = *(const ulonglong2*)&tvT[j * 132 + rm + 4];
            u64t av[4];
            av[0] = mul2(hv2[0], t0.x);
            av[1] = mul2(hv2[1], t0.y);
            av[2] = mul2(hv2[2], t1.x);
            av[3] = mul2(hv2[3], t1.y);
            float wf[8];
            *(float4*)&wf[0] = *(const float4*)&Ws[j * 128 + rn];
            *(float4*)&wf[4] = *(const float4*)&Ws[j * 128 + rn + 4];
#pragma unroll
            for (int jj = 0; jj < 8; jj++) {
                u64t wb = pack2b(wf[jj]);
#pragma unroll
                for (int ii2 = 0; ii2 < 4; ii2++) fma2(acc2[ii2][jj], av[ii2], wb);
            }
        }
    }

    float* P = g_part + (size_t)kb * NP * CQ;
#pragma unroll
    for (int ii2 = 0; ii2 < 4; ii2++) {
        int row0 = p0 + rm + 2 * ii2;
#pragma unroll
        for (int jj = 0; jj < 8; jj++) {
            int c = rn + jj;
            if (c < CQ) {
                float2 v = unpack2(acc2[ii2][jj]);
                P[(size_t)row0 * CQ + c]       = v.x;
                P[(size_t)(row0 + 1) * CQ + c] = v.y;
            }
        }
    }
}

// ---------------------------------------------------------------------------
// K7: deterministic split-K reduction + bias
// ---------------------------------------------------------------------------
__global__ void k_reduce(const float* __restrict__ bbias, float* __restrict__ out) {
    int idx = blockIdx.x * 256 + threadIdx.x;
    if (idx < NP * CQ) {
        int c = idx % CQ;
        float s = bbias[c];
#pragma unroll
        for (int z = 0; z < NKB; z++) s += g_part[(size_t)z * NP * CQ + idx];
        out[idx] = s;
    }
}

// ---------------------------------------------------------------------------
extern "C" void kernel_launch(void* const* d_in, const int* in_sizes, int n_in,
                              void* d_out, int out_size) {
    const float* seq     = (const float*)d_in[0];   // [B,L,H]
    const float* ent_lhs = (const float*)d_in[1];   // [B,M,H]
    const float* attn    = (const float*)d_in[2];   // [B,NH,M,L]
    const int*   labels  = (const int*)d_in[3];     // [B,M]
    const int*   hts     = (const int*)d_in[4];     // [B,R,2]
    const float* Wh      = (const float*)d_in[5];   // [2H,D]
    const float* bh      = (const float*)d_in[6];   // [D]
    const float* Wt      = (const float*)d_in[7];
    const float* bt      = (const float*)d_in[8];
    const float* Wb      = (const float*)d_in[9];   // [D*BLK,C]
    const float* bbias   = (const float*)d_in[10];  // [C]
    float* out = (float*)d_out;

    const int FIN_SMEM = (2 * 64 * 132 + 64 * 128) * 4;  // 100352 bytes
    cudaFuncSetAttribute(gemm_final, cudaFuncAttributeMaxDynamicSharedMemorySize, FIN_SMEM);

    k_build<<<BQ, EQ>>>(labels);
    k_ent_emb<<<BQ * EQ, 256>>>(ent_lhs);
    k_ent_attn<<<dim3(NHQ, BQ * EQ), 128>>>(attn);
    k_ht<<<NP, 128>>>(hts);
    gemm_rel<<<dim3(HQ / 128, RQ / 128, BQ), 256>>>(seq);
    gemm_extract<<<dim3(DQ / 128, NP / 128, 2), 256>>>(hts, Wh, bh, Wt, bt);
    gemm_final<<<dim3(NP / 128, NKB), 256, FIN_SMEM>>>(Wb);
    k_reduce<<<(NP * CQ + 255) / 256, 256>>>(bbias, out);
}

// round 9
// speedup vs baseline: 1.2929x; 1.1433x over previous
#include <cuda_runtime.h>
#include <math.h>

// Problem constants
#define BQ 4
#define LQ 512
#define HQ 1024
#define MQ 128
#define EQ 64
#define NHQ 16
#define RQ 1024
#define DQ 768
#define BLKQ 64
#define CQ 97
#define NKB 12           // D / BLK
#define NP (BQ * RQ)     // 4096 pairs
#define NEQ (BQ * EQ)    // 256 distinct entities
#define NPAD 104         // padded class dim (13 * 8), covers C=97

// -------- scratch (static device globals: allocation-guard safe) ----------
__device__ float g_ent_emb[NEQ * HQ];              // 1 MB
__device__ int   g_cnt[NEQ];
__device__ int   g_list[NEQ * MQ];
__device__ float g_ent_attn[NEQ * NHQ * LQ];       // 8 MB
__device__ float g_ht[NP * LQ];                    // 8 MB
__device__ float g_rel[NP * HQ];                   // 16 MB
__device__ float g_hv[NP * DQ];                    // 12 MB
__device__ float g_tv[NP * DQ];                    // 12 MB
__device__ float g_entW[2 * NEQ * DQ];             // 1.5 MB: ent_emb @ W_top + bias
__device__ float g_part[NKB * NP * CQ];            // 19 MB split-K partials

// -------- packed f32x2 helpers (sm_100+: FFMA2 only reachable via PTX) ----
typedef unsigned long long u64t;

__device__ __forceinline__ u64t pack2b(float v) {           // {v, v}
    u64t r; asm("mov.b64 %0, {%1, %1};" : "=l"(r) : "f"(v)); return r;
}
__device__ __forceinline__ u64t mul2(u64t a, u64t b) {
    u64t r; asm("mul.rn.f32x2 %0, %1, %2;" : "=l"(r) : "l"(a), "l"(b)); return r;
}
__device__ __forceinline__ void fma2(u64t& d, u64t a, u64t b) {
    asm("fma.rn.f32x2 %0, %1, %2, %0;" : "+l"(d) : "l"(a), "l"(b));
}
__device__ __forceinline__ float2 unpack2(u64t v) {
    float2 r; asm("mov.b64 {%0, %1}, %2;" : "=f"(r.x), "=f"(r.y) : "l"(v)); return r;
}

// ---------------------------------------------------------------------------
// K0: per (b,e) mention index lists
// ---------------------------------------------------------------------------
__global__ void k_build(const int* __restrict__ labels) {
    int b = blockIdx.x, e = threadIdx.x;       // grid: B, block: E
    int c = 0;
    int* lst = g_list + (b * EQ + e) * MQ;
    for (int m = 0; m < MQ; m++)
        if (labels[b * MQ + m] == e) lst[c++] = m;
    g_cnt[b * EQ + e] = c;
}

// ---------------------------------------------------------------------------
// K1: segment logsumexp over mentions -> ent_emb [B,E,H]
// ---------------------------------------------------------------------------
__global__ void k_ent_emb(const float* __restrict__ ent_lhs) {
    int be = blockIdx.x;                 // grid: B*E, block: 256
    int b = be / EQ;
    __shared__ int s_list[MQ];
    int cnt = g_cnt[be];
    for (int i = threadIdx.x; i < cnt; i += 256) s_list[i] = g_list[be * MQ + i];
    __syncthreads();
    const float* base = ent_lhs + (size_t)b * MQ * HQ;
    for (int h = threadIdx.x; h < HQ; h += 256) {
        float o = 0.f;
        if (cnt > 0) {
            float mx = -3.4e38f;
            for (int i = 0; i < cnt; i++) mx = fmaxf(mx, base[s_list[i] * HQ + h]);
            float s = 0.f;
            for (int i = 0; i < cnt; i++) s += expf(base[s_list[i] * HQ + h] - mx);
            o = mx + logf(s);
        }
        g_ent_emb[be * HQ + h] = o;
    }
}

// ---------------------------------------------------------------------------
// K2: mean mention attention -> ent_attn [B,E,NH,L]
// ---------------------------------------------------------------------------
__global__ void k_ent_attn(const float* __restrict__ attn) {
    int be = blockIdx.y, nh = blockIdx.x;   // grid: (NH, B*E), block: 128
    int b = be / EQ;
    int cnt = g_cnt[be];
    __shared__ int s_list[MQ];
    for (int i = threadIdx.x; i < cnt; i += 128) s_list[i] = g_list[be * MQ + i];
    __syncthreads();
    float inv = (cnt > 0) ? 1.f / (float)cnt : 0.f;
    const float* abase = attn + ((size_t)(b * NHQ + nh)) * MQ * LQ;
    float* obase = g_ent_attn + ((size_t)(be * NHQ + nh)) * LQ;
    for (int l = threadIdx.x; l < LQ; l += 128) {
        float s = 0.f;
        for (int i = 0; i < cnt; i++) s += abase[s_list[i] * LQ + l];
        obase[l] = s * inv;
    }
}

// ---------------------------------------------------------------------------
// K3: pair attention product, mean over heads, normalize -> g_ht [NP,L]
// ---------------------------------------------------------------------------
__global__ void k_ht(const int* __restrict__ hts) {
    int n = blockIdx.x;                 // grid: NP, block: 128
    int b = n / RQ;
    int he = hts[n * 2 + 0];
    int te = hts[n * 2 + 1];
    const float* ha = g_ent_attn + ((size_t)(b * EQ + he)) * NHQ * LQ;
    const float* ta = g_ent_attn + ((size_t)(b * EQ + te)) * NHQ * LQ;
    float v[4];
    float loc = 0.f;
#pragma unroll
    for (int rep = 0; rep < 4; rep++) {
        int l = threadIdx.x + rep * 128;
        float acc = 0.f;
#pragma unroll
        for (int nh = 0; nh < NHQ; nh++) acc += ha[nh * LQ + l] * ta[nh * LQ + l];
        v[rep] = acc * (1.0f / NHQ);
        loc += v[rep];
    }
    __shared__ float red[128];
    red[threadIdx.x] = loc;
    __syncthreads();
    for (int s = 64; s > 0; s >>= 1) {
        if (threadIdx.x < s) red[threadIdx.x] += red[threadIdx.x + s];
        __syncthreads();
    }
    float inv = 1.f / (red[0] + 1e-5f);
#pragma unroll
    for (int rep = 0; rep < 4; rep++)
        g_ht[(size_t)n * LQ + threadIdx.x + rep * 128] = v[rep] * inv;
}

// ---------------------------------------------------------------------------
// K4: rel = ht_attn @ seq_lhs    (batched 1024x1024x512)
// 128x128x16 tile, 256 threads, 8x8 microtile, f32x2 FMA (pack along j)
// ---------------------------------------------------------------------------
__global__ __launch_bounds__(256) void gemm_rel(const float* __restrict__ seq) {
    int b = blockIdx.z;
    int n0 = blockIdx.x * 128;   // column in H
    int r0 = blockIdx.y * 128;   // row within batch
    __shared__ float As[16][128];
    __shared__ float Bsh[16][128];
    u64t acc2[8][4];
#pragma unroll
    for (int i = 0; i < 8; i++)
#pragma unroll
        for (int j = 0; j < 4; j++) acc2[i][j] = 0ULL;

    int tid = threadIdx.x;
    int arow = tid >> 1, akc = (tid & 1) * 8;
    int brow = tid >> 4, bcc = (tid & 15) * 8;
    int rm = (tid >> 4) * 8, rn = (tid & 15) * 8;
    const float* Abase = g_ht + (size_t)(b * RQ + r0) * LQ;
    const float* Bbase = seq + (size_t)b * LQ * HQ + n0;

    for (int k0 = 0; k0 < LQ; k0 += 16) {
        float4 a0 = *(const float4*)(Abase + (size_t)arow * LQ + k0 + akc);
        float4 a1 = *(const float4*)(Abase + (size_t)arow * LQ + k0 + akc + 4);
        float4 b0 = *(const float4*)(Bbase + (size_t)(k0 + brow) * HQ + bcc);
        float4 b1 = *(const float4*)(Bbase + (size_t)(k0 + brow) * HQ + bcc + 4);
        __syncthreads();
        As[akc + 0][arow] = a0.x; As[akc + 1][arow] = a0.y;
        As[akc + 2][arow] = a0.z; As[akc + 3][arow] = a0.w;
        As[akc + 4][arow] = a1.x; As[akc + 5][arow] = a1.y;
        As[akc + 6][arow] = a1.z; As[akc + 7][arow] = a1.w;
        *(float4*)&Bsh[brow][bcc] = b0;
        *(float4*)&Bsh[brow][bcc + 4] = b1;
        __syncthreads();
#pragma unroll
        for (int kk = 0; kk < 16; kk++) {
            float a[8];
            *(float4*)&a[0] = *(const float4*)&As[kk][rm];
            *(float4*)&a[4] = *(const float4*)&As[kk][rm + 4];
            ulonglong2 bu0 = *(const ulonglong2*)&Bsh[kk][rn];
            ulonglong2 bu1 = *(const ulonglong2*)&Bsh[kk][rn + 4];
            u64t b2[4] = {bu0.x, bu0.y, bu1.x, bu1.y};
#pragma unroll
            for (int i = 0; i < 8; i++) {
                u64t a2 = pack2b(a[i]);
#pragma unroll
                for (int j = 0; j < 4; j++) fma2(acc2[i][j], a2, b2[j]);
            }
        }
    }
    float* Cb = g_rel + (size_t)(b * RQ + r0) * HQ + n0;
#pragma unroll
    for (int i = 0; i < 8; i++)
#pragma unroll
        for (int j = 0; j < 4; j++) {
            float2 v = unpack2(acc2[i][j]);
            *(float2*)&Cb[(size_t)(rm + i) * HQ + rn + 2 * j] = v;
        }
}

// ---------------------------------------------------------------------------
// K5a: entW[z, be, :] = ent_emb[be] @ W_top + bias   (256 x 1024 x 768, z=0/1)
// Tiny GEMM (0.4 G-FMA) that removes half the K-dim of the per-pair extract.
// ---------------------------------------------------------------------------
__global__ __launch_bounds__(256) void gemm_ent(
    const float* __restrict__ Wh, const float* __restrict__ bh,
    const float* __restrict__ Wt, const float* __restrict__ bt) {
    int z = blockIdx.z;
    int n0 = blockIdx.x * 128;    // column in D
    int r0 = blockIdx.y * 128;    // entity row
    const float* W = z ? Wt : Wh;       // use rows [0, HQ)
    const float* bias = z ? bt : bh;

    __shared__ float As[16][128];
    __shared__ float Bsh[16][128];
    int tid = threadIdx.x;
    u64t acc2[8][4];
#pragma unroll
    for (int i = 0; i < 8; i++)
#pragma unroll
        for (int j = 0; j < 4; j++) acc2[i][j] = 0ULL;

    int arow = tid >> 1, akc = (tid & 1) * 8;
    int brow = tid >> 4, bcc = (tid & 15) * 8;
    int rm = (tid >> 4) * 8, rn = (tid & 15) * 8;
    const float* Abase = g_ent_emb + (size_t)r0 * HQ;

    for (int k0 = 0; k0 < HQ; k0 += 16) {
        float4 a0 = *(const float4*)(Abase + (size_t)arow * HQ + k0 + akc);
        float4 a1 = *(const float4*)(Abase + (size_t)arow * HQ + k0 + akc + 4);
        float4 b0 = *(const float4*)(W + (size_t)(k0 + brow) * DQ + n0 + bcc);
        float4 b1 = *(const float4*)(W + (size_t)(k0 + brow) * DQ + n0 + bcc + 4);
        __syncthreads();
        As[akc + 0][arow] = a0.x; As[akc + 1][arow] = a0.y;
        As[akc + 2][arow] = a0.z; As[akc + 3][arow] = a0.w;
        As[akc + 4][arow] = a1.x; As[akc + 5][arow] = a1.y;
        As[akc + 6][arow] = a1.z; As[akc + 7][arow] = a1.w;
        *(float4*)&Bsh[brow][bcc] = b0;
        *(float4*)&Bsh[brow][bcc + 4] = b1;
        __syncthreads();
#pragma unroll
        for (int kk = 0; kk < 16; kk++) {
            float a[8];
            *(float4*)&a[0] = *(const float4*)&As[kk][rm];
            *(float4*)&a[4] = *(const float4*)&As[kk][rm + 4];
            ulonglong2 bu0 = *(const ulonglong2*)&Bsh[kk][rn];
            ulonglong2 bu1 = *(const ulonglong2*)&Bsh[kk][rn + 4];
            u64t b2[4] = {bu0.x, bu0.y, bu1.x, bu1.y};
#pragma unroll
            for (int i = 0; i < 8; i++) {
                u64t a2 = pack2b(a[i]);
#pragma unroll
                for (int j = 0; j < 4; j++) fma2(acc2[i][j], a2, b2[j]);
            }
        }
    }
    float* Cb = g_entW + ((size_t)z * NEQ + r0) * DQ + n0;
#pragma unroll
    for (int i = 0; i < 8; i++)
#pragma unroll
        for (int j = 0; j < 4; j++) {
            float2 v = unpack2(acc2[i][j]);
            int col = rn + 2 * j;
            Cb[(size_t)(rm + i) * DQ + col]     = v.x + bias[n0 + col];
            Cb[(size_t)(rm + i) * DQ + col + 1] = v.y + bias[n0 + col + 1];
        }
}

// ---------------------------------------------------------------------------
// K5b: hv/tv = tanh(rel @ W_bot + gathered entW)     K = 1024 only
// ---------------------------------------------------------------------------
__global__ __launch_bounds__(256) void gemm_extract(
    const int* __restrict__ hts,
    const float* __restrict__ Wh, const float* __restrict__ Wt) {
    int z = blockIdx.z;
    int n0 = blockIdx.x * 128;    // column in D
    int p0 = blockIdx.y * 128;    // global pair row
    const float* W = (z ? Wt : Wh) + (size_t)HQ * DQ;   // bottom half rows
    float* C = z ? g_tv : g_hv;

    __shared__ float As[16][128];
    __shared__ float Bsh[16][128];
    __shared__ int s_eoff[128];   // entW row offset per tile row
    int tid = threadIdx.x;
    if (tid < 128) {
        int n = p0 + tid;
        int b = n / RQ;
        int e = hts[n * 2 + z];
        s_eoff[tid] = (z * NEQ + b * EQ + e) * DQ;
    }
    __syncthreads();

    u64t acc2[8][4];
#pragma unroll
    for (int i = 0; i < 8; i++)
#pragma unroll
        for (int j = 0; j < 4; j++) acc2[i][j] = 0ULL;

    int arow = tid >> 1, akc = (tid & 1) * 8;
    int brow = tid >> 4, bcc = (tid & 15) * 8;
    int rm = (tid >> 4) * 8, rn = (tid & 15) * 8;
    const float* Abase = g_rel + (size_t)p0 * HQ;

    for (int k0 = 0; k0 < HQ; k0 += 16) {
        float4 a0 = *(const float4*)(Abase + (size_t)arow * HQ + k0 + akc);
        float4 a1 = *(const float4*)(Abase + (size_t)arow * HQ + k0 + akc + 4);
        float4 b0 = *(const float4*)(W + (size_t)(k0 + brow) * DQ + n0 + bcc);
        float4 b1 = *(const float4*)(W + (size_t)(k0 + brow) * DQ + n0 + bcc + 4);
        __syncthreads();
        As[akc + 0][arow] = a0.x; As[akc + 1][arow] = a0.y;
        As[akc + 2][arow] = a0.z; As[akc + 3][arow] = a0.w;
        As[akc + 4][arow] = a1.x; As[akc + 5][arow] = a1.y;
        As[akc + 6][arow] = a1.z; As[akc + 7][arow] = a1.w;
        *(float4*)&Bsh[brow][bcc] = b0;
        *(float4*)&Bsh[brow][bcc + 4] = b1;
        __syncthreads();
#pragma unroll
        for (int kk = 0; kk < 16; kk++) {
            float a[8];
            *(float4*)&a[0] = *(const float4*)&As[kk][rm];
            *(float4*)&a[4] = *(const float4*)&As[kk][rm + 4];
            ulonglong2 bu0 = *(const ulonglong2*)&Bsh[kk][rn];
            ulonglong2 bu1 = *(const ulonglong2*)&Bsh[kk][rn + 4];
            u64t b2[4] = {bu0.x, bu0.y, bu1.x, bu1.y};
#pragma unroll
            for (int i = 0; i < 8; i++) {
                u64t a2 = pack2b(a[i]);
#pragma unroll
                for (int j = 0; j < 4; j++) fma2(acc2[i][j], a2, b2[j]);
            }
        }
    }
#pragma unroll
    for (int i = 0; i < 8; i++) {
        int row = p0 + rm + i;
        const float* ew = g_entW + s_eoff[rm + i] + n0;
#pragma unroll
        for (int j = 0; j < 4; j++) {
            float2 v = unpack2(acc2[i][j]);
            int col = rn + 2 * j;
            C[(size_t)row * DQ + n0 + col]     = tanhf(v.x + ew[col]);
            C[(size_t)row * DQ + n0 + col + 1] = tanhf(v.y + ew[col + 1]);
        }
    }
}

// ---------------------------------------------------------------------------
// K6: final block-bilinear GEMM, f32x2 FMA, N padded to 104 (was 128).
// out[n,c] = sum_{k,i,j} hv[n,k*64+i] * tv[n,k*64+j] * Wb[k*4096+i*64+j, c]
// Column group in HIGH tid bits: warp 7 fully idle (skips j-loop), warp 6 half.
// Split-K over k (12 blocks) into g_part.
// dynamic smem: tvT[64][132] + hvT[64][132] + Ws[64][104] = 94208 B -> 2 CTA/SM
// ---------------------------------------------------------------------------
extern __shared__ float s_fin[];
__global__ __launch_bounds__(256) void gemm_final(const float* __restrict__ Wb) {
    int p0 = blockIdx.x * 128;
    int kb = blockIdx.y;
    float* tvT = s_fin;                  // [64][132] j-major
    float* hvT = s_fin + 64 * 132;       // [64][132] i-major
    float* Ws  = s_fin + 2 * 64 * 132;   // [64][NPAD]
    int tid = threadIdx.x;

    // load hv/tv tiles (once per block: kb fixed), transposed
#pragma unroll
    for (int it = 0; it < 8; it++) {
        int idx = tid + it * 256;        // 0..2047 float4 slots
        int row = idx >> 4;
        int c4 = (idx & 15) * 4;
        const float* hp = g_hv + (size_t)(p0 + row) * DQ + kb * 64 + c4;
        const float* tp = g_tv + (size_t)(p0 + row) * DQ + kb * 64 + c4;
        float4 h4 = *(const float4*)hp;
        float4 t4 = *(const float4*)tp;
        hvT[(c4 + 0) * 132 + row] = h4.x; hvT[(c4 + 1) * 132 + row] = h4.y;
        hvT[(c4 + 2) * 132 + row] = h4.z; hvT[(c4 + 3) * 132 + row] = h4.w;
        tvT[(c4 + 0) * 132 + row] = t4.x; tvT[(c4 + 1) * 132 + row] = t4.y;
        tvT[(c4 + 2) * 132 + row] = t4.z; tvT[(c4 + 3) * 132 + row] = t4.w;
    }

    u64t acc2[4][8];                     // [row-pair ii2][col jj]
#pragma unroll
    for (int i = 0; i < 4; i++)
#pragma unroll
        for (int j = 0; j < 8; j++) acc2[i][j] = 0ULL;

    // column group in HIGH bits: warps 0..5 full, warp 6 half, warp 7 idle
    int rm = (tid & 15) * 8;
    int cn = tid >> 4;
    int rn = cn * 8;
    bool active = (cn < 13);
    const float* Wbase = Wb + (size_t)kb * 4096 * CQ;

    for (int i = 0; i < 64; i++) {
        __syncthreads();   // previous stage compute done (and tile loads on i==0)
        // stage Wb slab for (kb, i): rows j=0..63, padded cols 0..NPAD-1
        for (int t = tid; t < 64 * NPAD; t += 256) {
            int j = t / NPAD, c = t % NPAD;
            Ws[t] = (c < CQ) ? Wbase[(size_t)(i * 64 + j) * CQ + c] : 0.f;
        }
        __syncthreads();
        if (!active) continue;
        ulonglong2 h0 = *(const ulonglong2*)&hvT[i * 132 + rm];
        ulonglong2 h1 = *(const ulonglong2*)&hvT[i * 132 + rm + 4];
        u64t hv2[4] = {h0.x, h0.y, h1.x, h1.y};
#pragma unroll 4
        for (int j = 0; j < 64; j++) {
            ulonglong2 t0 = *(const ulonglong2*)&tvT[j * 132 + rm];
            ulonglong2 t1 = *(const ulonglong2*)&tvT[j * 132 + rm + 4];
            u64t av[4];
            av[0] = mul2(hv2[0], t0.x);
            av[1] = mul2(hv2[1], t0.y);
            av[2] = mul2(hv2[2], t1.x);
            av[3] = mul2(hv2[3], t1.y);
            float wf[8];
            *(float4*)&wf[0] = *(const float4*)&Ws[j * NPAD + rn];
            *(float4*)&wf[4] = *(const float4*)&Ws[j * NPAD + rn + 4];
#pragma unroll
            for (int jj = 0; jj < 8; jj++) {
                u64t wb = pack2b(wf[jj]);
#pragma unroll
                for (int ii2 = 0; ii2 < 4; ii2++) fma2(acc2[ii2][jj], av[ii2], wb);
            }
        }
    }

    if (active) {
        float* P = g_part + (size_t)kb * NP * CQ;
#pragma unroll
        for (int ii2 = 0; ii2 < 4; ii2++) {
            int row0 = p0 + rm + 2 * ii2;
#pragma unroll
            for (int jj = 0; jj < 8; jj++) {
                int c = rn + jj;
                if (c < CQ) {
                    float2 v = unpack2(acc2[ii2][jj]);
                    P[(size_t)row0 * CQ + c]       = v.x;
                    P[(size_t)(row0 + 1) * CQ + c] = v.y;
                }
            }
        }
    }
}

// ---------------------------------------------------------------------------
// K7: deterministic split-K reduction + bias
// ---------------------------------------------------------------------------
__global__ void k_reduce(const float* __restrict__ bbias, float* __restrict__ out) {
    int idx = blockIdx.x * 256 + threadIdx.x;
    if (idx < NP * CQ) {
        int c = idx % CQ;
        float s = bbias[c];
#pragma unroll
        for (int z = 0; z < NKB; z++) s += g_part[(size_t)z * NP * CQ + idx];
        out[idx] = s;
    }
}

// ---------------------------------------------------------------------------
extern "C" void kernel_launch(void* const* d_in, const int* in_sizes, int n_in,
                              void* d_out, int out_size) {
    const float* seq     = (const float*)d_in[0];   // [B,L,H]
    const float* ent_lhs = (const float*)d_in[1];   // [B,M,H]
    const float* attn    = (const float*)d_in[2];   // [B,NH,M,L]
    const int*   labels  = (const int*)d_in[3];     // [B,M]
    const int*   hts     = (const int*)d_in[4];     // [B,R,2]
    const float* Wh      = (const float*)d_in[5];   // [2H,D]
    const float* bh      = (const float*)d_in[6];   // [D]
    const float* Wt      = (const float*)d_in[7];
    const float* bt      = (const float*)d_in[8];
    const float* Wb      = (const float*)d_in[9];   // [D*BLK,C]
    const float* bbias   = (const float*)d_in[10];  // [C]
    float* out = (float*)d_out;

    const int FIN_SMEM = (2 * 64 * 132 + 64 * NPAD) * 4;  // 94208 bytes
    cudaFuncSetAttribute(gemm_final, cudaFuncAttributeMaxDynamicSharedMemorySize, FIN_SMEM);

    k_build<<<BQ, EQ>>>(labels);
    k_ent_emb<<<NEQ, 256>>>(ent_lhs);
    k_ent_attn<<<dim3(NHQ, NEQ), 128>>>(attn);
    k_ht<<<NP, 128>>>(hts);
    gemm_rel<<<dim3(HQ / 128, RQ / 128, BQ), 256>>>(seq);
    gemm_ent<<<dim3(DQ / 128, NEQ / 128, 2), 256>>>(Wh, bh, Wt, bt);
    gemm_extract<<<dim3(DQ / 128, NP / 128, 2), 256>>>(hts, Wh, Wt);
    gemm_final<<<dim3(NP / 128, NKB), 256, FIN_SMEM>>>(Wb);
    k_reduce<<<(NP * CQ + 255) / 256, 256>>>(bbias, out);
}

// round 11
// speedup vs baseline: 2.5311x; 1.9577x over previous
#include <cuda_runtime.h>
#include <cuda_bf16.h>
#include <math.h>
#include <stdint.h>

// Problem constants
#define BQ 4
#define LQ 512
#define HQ 1024
#define MQ 128
#define EQ 64
#define NHQ 16
#define RQ 1024
#define DQ 768
#define BLKQ 64
#define CQ 97
#define NKB 12           // D / BLK  (split-K planes)
#define NP (BQ * RQ)     // 4096 pairs
#define NEQ (BQ * EQ)    // 256 distinct entities
#define KTOT 49152       // D * BLK

// -------- scratch (static device globals: allocation-guard safe) ----------
__device__ float g_ent_emb[NEQ * HQ];              // 1 MB
__device__ int   g_cnt[NEQ];
__device__ int   g_list[NEQ * MQ];
__device__ float g_ent_attn[NEQ * NHQ * LQ];       // 8 MB
__device__ float g_ht[NP * LQ];                    // 8 MB
__device__ float g_rel[NP * HQ];                   // 16 MB
__device__ float g_hv[NP * DQ];                    // 12 MB
__device__ float g_tv[NP * DQ];                    // 12 MB
__device__ float g_entW[2 * NEQ * DQ];             // 1.5 MB
__device__ float g_part[NKB * NP * CQ];            // 19 MB split-K partials
__device__ __nv_bfloat16 g_WbB_h[KTOT * 128];      // 12.6 MB  Wb k-major hi split
__device__ __nv_bfloat16 g_WbB_l[KTOT * 128];      // 12.6 MB  Wb k-major lo split

// -------- packed f32x2 helpers ----
typedef unsigned long long u64t;

__device__ __forceinline__ u64t pack2b(float v) {
    u64t r; asm("mov.b64 %0, {%1, %1};" : "=l"(r) : "f"(v)); return r;
}
__device__ __forceinline__ void fma2(u64t& d, u64t a, u64t b) {
    asm("fma.rn.f32x2 %0, %1, %2, %0;" : "+l"(d) : "l"(a), "l"(b));
}
__device__ __forceinline__ float2 unpack2(u64t v) {
    float2 r; asm("mov.b64 {%0, %1}, %2;" : "=f"(r.x), "=f"(r.y) : "l"(v)); return r;
}

// -------- HMMA helpers (base-target legal: mma.sync + ldmatrix) ----
__device__ __forceinline__ uint32_t smem_u32(const void* p) {
    return (uint32_t)__cvta_generic_to_shared(p);
}
__device__ __forceinline__ void mma16816(float* d, uint32_t a0, uint32_t a1,
                                         uint32_t a2, uint32_t a3,
                                         uint32_t b0, uint32_t b1) {
    asm volatile(
        "mma.sync.aligned.m16n8k16.row.col.f32.bf16.bf16.f32 "
        "{%0,%1,%2,%3}, {%4,%5,%6,%7}, {%8,%9}, {%0,%1,%2,%3};"
        : "+f"(d[0]), "+f"(d[1]), "+f"(d[2]), "+f"(d[3])
        : "r"(a0), "r"(a1), "r"(a2), "r"(a3), "r"(b0), "r"(b1));
}
__device__ __forceinline__ void ldsm2t(uint32_t& r0, uint32_t& r1, uint32_t addr) {
    asm volatile("ldmatrix.sync.aligned.m8n8.x2.trans.shared.b16 {%0,%1}, [%2];"
                 : "=r"(r0), "=r"(r1) : "r"(addr));
}
__device__ __forceinline__ uint32_t bfpack(float lo, float hi) {
    __nv_bfloat162 t = __floats2bfloat162_rn(lo, hi);
    return *(uint32_t*)&t;
}

// ---------------------------------------------------------------------------
// K0: per (b,e) mention index lists
// ---------------------------------------------------------------------------
__global__ void k_build(const int* __restrict__ labels) {
    int b = blockIdx.x, e = threadIdx.x;
    int c = 0;
    int* lst = g_list + (b * EQ + e) * MQ;
    for (int m = 0; m < MQ; m++)
        if (labels[b * MQ + m] == e) lst[c++] = m;
    g_cnt[b * EQ + e] = c;
}

// ---------------------------------------------------------------------------
// K1: segment logsumexp over mentions -> ent_emb [B,E,H]
// ---------------------------------------------------------------------------
__global__ void k_ent_emb(const float* __restrict__ ent_lhs) {
    int be = blockIdx.x;
    int b = be / EQ;
    __shared__ int s_list[MQ];
    int cnt = g_cnt[be];
    for (int i = threadIdx.x; i < cnt; i += 256) s_list[i] = g_list[be * MQ + i];
    __syncthreads();
    const float* base = ent_lhs + (size_t)b * MQ * HQ;
    for (int h = threadIdx.x; h < HQ; h += 256) {
        float o = 0.f;
        if (cnt > 0) {
            float mx = -3.4e38f;
            for (int i = 0; i < cnt; i++) mx = fmaxf(mx, base[s_list[i] * HQ + h]);
            float s = 0.f;
            for (int i = 0; i < cnt; i++) s += expf(base[s_list[i] * HQ + h] - mx);
            o = mx + logf(s);
        }
        g_ent_emb[be * HQ + h] = o;
    }
}

// ---------------------------------------------------------------------------
// K2: mean mention attention -> ent_attn [B,E,NH,L]
// ---------------------------------------------------------------------------
__global__ void k_ent_attn(const float* __restrict__ attn) {
    int be = blockIdx.y, nh = blockIdx.x;
    int b = be / EQ;
    int cnt = g_cnt[be];
    __shared__ int s_list[MQ];
    for (int i = threadIdx.x; i < cnt; i += 128) s_list[i] = g_list[be * MQ + i];
    __syncthreads();
    float inv = (cnt > 0) ? 1.f / (float)cnt : 0.f;
    const float* abase = attn + ((size_t)(b * NHQ + nh)) * MQ * LQ;
    float* obase = g_ent_attn + ((size_t)(be * NHQ + nh)) * LQ;
    for (int l = threadIdx.x; l < LQ; l += 128) {
        float s = 0.f;
        for (int i = 0; i < cnt; i++) s += abase[s_list[i] * LQ + l];
        obase[l] = s * inv;
    }
}

// ---------------------------------------------------------------------------
// K3: pair attention product, mean over heads, normalize -> g_ht [NP,L]
// ---------------------------------------------------------------------------
__global__ void k_ht(const int* __restrict__ hts) {
    int n = blockIdx.x;
    int b = n / RQ;
    int he = hts[n * 2 + 0];
    int te = hts[n * 2 + 1];
    const float* ha = g_ent_attn + ((size_t)(b * EQ + he)) * NHQ * LQ;
    const float* ta = g_ent_attn + ((size_t)(b * EQ + te)) * NHQ * LQ;
    float v[4];
    float loc = 0.f;
#pragma unroll
    for (int rep = 0; rep < 4; rep++) {
        int l = threadIdx.x + rep * 128;
        float acc = 0.f;
#pragma unroll
        for (int nh = 0; nh < NHQ; nh++) acc += ha[nh * LQ + l] * ta[nh * LQ + l];
        v[rep] = acc * (1.0f / NHQ);
        loc += v[rep];
    }
    __shared__ float red[128];
    red[threadIdx.x] = loc;
    __syncthreads();
    for (int s = 64; s > 0; s >>= 1) {
        if (threadIdx.x < s) red[threadIdx.x] += red[threadIdx.x + s];
        __syncthreads();
    }
    float inv = 1.f / (red[0] + 1e-5f);
#pragma unroll
    for (int rep = 0; rep < 4; rep++)
        g_ht[(size_t)n * LQ + threadIdx.x + rep * 128] = v[rep] * inv;
}

// ---------------------------------------------------------------------------
// K4: rel = ht_attn @ seq_lhs    (batched 1024x1024x512) — f32x2
// ---------------------------------------------------------------------------
__global__ __launch_bounds__(256) void gemm_rel(const float* __restrict__ seq) {
    int b = blockIdx.z;
    int n0 = blockIdx.x * 128;
    int r0 = blockIdx.y * 128;
    __shared__ float As[16][128];
    __shared__ float Bsh[16][128];
    u64t acc2[8][4];
#pragma unroll
    for (int i = 0; i < 8; i++)
#pragma unroll
        for (int j = 0; j < 4; j++) acc2[i][j] = 0ULL;

    int tid = threadIdx.x;
    int arow = tid >> 1, akc = (tid & 1) * 8;
    int brow = tid >> 4, bcc = (tid & 15) * 8;
    int rm = (tid >> 4) * 8, rn = (tid & 15) * 8;
    const float* Abase = g_ht + (size_t)(b * RQ + r0) * LQ;
    const float* Bbase = seq + (size_t)b * LQ * HQ + n0;

    for (int k0 = 0; k0 < LQ; k0 += 16) {
        float4 a0 = *(const float4*)(Abase + (size_t)arow * LQ + k0 + akc);
        float4 a1 = *(const float4*)(Abase + (size_t)arow * LQ + k0 + akc + 4);
        float4 b0 = *(const float4*)(Bbase + (size_t)(k0 + brow) * HQ + bcc);
        float4 b1 = *(const float4*)(Bbase + (size_t)(k0 + brow) * HQ + bcc + 4);
        __syncthreads();
        As[akc + 0][arow] = a0.x; As[akc + 1][arow] = a0.y;
        As[akc + 2][arow] = a0.z; As[akc + 3][arow] = a0.w;
        As[akc + 4][arow] = a1.x; As[akc + 5][arow] = a1.y;
        As[akc + 6][arow] = a1.z; As[akc + 7][arow] = a1.w;
        *(float4*)&Bsh[brow][bcc] = b0;
        *(float4*)&Bsh[brow][bcc + 4] = b1;
        __syncthreads();
#pragma unroll
        for (int kk = 0; kk < 16; kk++) {
            float a[8];
            *(float4*)&a[0] = *(const float4*)&As[kk][rm];
            *(float4*)&a[4] = *(const float4*)&As[kk][rm + 4];
            ulonglong2 bu0 = *(const ulonglong2*)&Bsh[kk][rn];
            ulonglong2 bu1 = *(const ulonglong2*)&Bsh[kk][rn + 4];
            u64t b2[4] = {bu0.x, bu0.y, bu1.x, bu1.y};
#pragma unroll
            for (int i = 0; i < 8; i++) {
                u64t a2 = pack2b(a[i]);
#pragma unroll
                for (int j = 0; j < 4; j++) fma2(acc2[i][j], a2, b2[j]);
            }
        }
    }
    float* Cb = g_rel + (size_t)(b * RQ + r0) * HQ + n0;
#pragma unroll
    for (int i = 0; i < 8; i++)
#pragma unroll
        for (int j = 0; j < 4; j++) {
            float2 v = unpack2(acc2[i][j]);
            *(float2*)&Cb[(size_t)(rm + i) * HQ + rn + 2 * j] = v;
        }
}

// ---------------------------------------------------------------------------
// K5a: entW[z, be, :] = ent_emb[be] @ W_top + bias
// ---------------------------------------------------------------------------
__global__ __launch_bounds__(256) void gemm_ent(
    const float* __restrict__ Wh, const float* __restrict__ bh,
    const float* __restrict__ Wt, const float* __restrict__ bt) {
    int z = blockIdx.z;
    int n0 = blockIdx.x * 128;
    int r0 = blockIdx.y * 128;
    const float* W = z ? Wt : Wh;
    const float* bias = z ? bt : bh;

    __shared__ float As[16][128];
    __shared__ float Bsh[16][128];
    int tid = threadIdx.x;
    u64t acc2[8][4];
#pragma unroll
    for (int i = 0; i < 8; i++)
#pragma unroll
        for (int j = 0; j < 4; j++) acc2[i][j] = 0ULL;

    int arow = tid >> 1, akc = (tid & 1) * 8;
    int brow = tid >> 4, bcc = (tid & 15) * 8;
    int rm = (tid >> 4) * 8, rn = (tid & 15) * 8;
    const float* Abase = g_ent_emb + (size_t)r0 * HQ;

    for (int k0 = 0; k0 < HQ; k0 += 16) {
        float4 a0 = *(const float4*)(Abase + (size_t)arow * HQ + k0 + akc);
        float4 a1 = *(const float4*)(Abase + (size_t)arow * HQ + k0 + akc + 4);
        float4 b0 = *(const float4*)(W + (size_t)(k0 + brow) * DQ + n0 + bcc);
        float4 b1 = *(const float4*)(W + (size_t)(k0 + brow) * DQ + n0 + bcc + 4);
        __syncthreads();
        As[akc + 0][arow] = a0.x; As[akc + 1][arow] = a0.y;
        As[akc + 2][arow] = a0.z; As[akc + 3][arow] = a0.w;
        As[akc + 4][arow] = a1.x; As[akc + 5][arow] = a1.y;
        As[akc + 6][arow] = a1.z; As[akc + 7][arow] = a1.w;
        *(float4*)&Bsh[brow][bcc] = b0;
        *(float4*)&Bsh[brow][bcc + 4] = b1;
        __syncthreads();
#pragma unroll
        for (int kk = 0; kk < 16; kk++) {
            float a[8];
            *(float4*)&a[0] = *(const float4*)&As[kk][rm];
            *(float4*)&a[4] = *(const float4*)&As[kk][rm + 4];
            ulonglong2 bu0 = *(const ulonglong2*)&Bsh[kk][rn];
            ulonglong2 bu1 = *(const ulonglong2*)&Bsh[kk][rn + 4];
            u64t b2[4] = {bu0.x, bu0.y, bu1.x, bu1.y};
#pragma unroll
            for (int i = 0; i < 8; i++) {
                u64t a2 = pack2b(a[i]);
#pragma unroll
                for (int j = 0; j < 4; j++) fma2(acc2[i][j], a2, b2[j]);
            }
        }
    }
    float* Cb = g_entW + ((size_t)z * NEQ + r0) * DQ + n0;
#pragma unroll
    for (int i = 0; i < 8; i++)
#pragma unroll
        for (int j = 0; j < 4; j++) {
            float2 v = unpack2(acc2[i][j]);
            int col = rn + 2 * j;
            Cb[(size_t)(rm + i) * DQ + col]     = v.x + bias[n0 + col];
            Cb[(size_t)(rm + i) * DQ + col + 1] = v.y + bias[n0 + col + 1];
        }
}

// ---------------------------------------------------------------------------
// K5b: hv/tv = tanh(rel @ W_bot + gathered entW)     K = 1024
// ---------------------------------------------------------------------------
__global__ __launch_bounds__(256) void gemm_extract(
    const int* __restrict__ hts,
    const float* __restrict__ Wh, const float* __restrict__ Wt) {
    int z = blockIdx.z;
    int n0 = blockIdx.x * 128;
    int p0 = blockIdx.y * 128;
    const float* W = (z ? Wt : Wh) + (size_t)HQ * DQ;
    float* C = z ? g_tv : g_hv;

    __shared__ float As[16][128];
    __shared__ float Bsh[16][128];
    __shared__ int s_eoff[128];
    int tid = threadIdx.x;
    if (tid < 128) {
        int n = p0 + tid;
        int b = n / RQ;
        int e = hts[n * 2 + z];
        s_eoff[tid] = (z * NEQ + b * EQ + e) * DQ;
    }
    __syncthreads();

    u64t acc2[8][4];
#pragma unroll
    for (int i = 0; i < 8; i++)
#pragma unroll
        for (int j = 0; j < 4; j++) acc2[i][j] = 0ULL;

    int arow = tid >> 1, akc = (tid & 1) * 8;
    int brow = tid >> 4, bcc = (tid & 15) * 8;
    int rm = (tid >> 4) * 8, rn = (tid & 15) * 8;
    const float* Abase = g_rel + (size_t)p0 * HQ;

    for (int k0 = 0; k0 < HQ; k0 += 16) {
        float4 a0 = *(const float4*)(Abase + (size_t)arow * HQ + k0 + akc);
        float4 a1 = *(const float4*)(Abase + (size_t)arow * HQ + k0 + akc + 4);
        float4 b0 = *(const float4*)(W + (size_t)(k0 + brow) * DQ + n0 + bcc);
        float4 b1 = *(const float4*)(W + (size_t)(k0 + brow) * DQ + n0 + bcc + 4);
        __syncthreads();
        As[akc + 0][arow] = a0.x; As[akc + 1][arow] = a0.y;
        As[akc + 2][arow] = a0.z; As[akc + 3][arow] = a0.w;
        As[akc + 4][arow] = a1.x; As[akc + 5][arow] = a1.y;
        As[akc + 6][arow] = a1.z; As[akc + 7][arow] = a1.w;
        *(float4*)&Bsh[brow][bcc] = b0;
        *(float4*)&Bsh[brow][bcc + 4] = b1;
        __syncthreads();
#pragma unroll
        for (int kk = 0; kk < 16; kk++) {
            float a[8];
            *(float4*)&a[0] = *(const float4*)&As[kk][rm];
            *(float4*)&a[4] = *(const float4*)&As[kk][rm + 4];
            ulonglong2 bu0 = *(const ulonglong2*)&Bsh[kk][rn];
            ulonglong2 bu1 = *(const ulonglong2*)&Bsh[kk][rn + 4];
            u64t b2[4] = {bu0.x, bu0.y, bu1.x, bu1.y};
#pragma unroll
            for (int i = 0; i < 8; i++) {
                u64t a2 = pack2b(a[i]);
#pragma unroll
                for (int j = 0; j < 4; j++) fma2(acc2[i][j], a2, b2[j]);
            }
        }
    }
#pragma unroll
    for (int i = 0; i < 8; i++) {
        int row = p0 + rm + i;
        const float* ew = g_entW + s_eoff[rm + i] + n0;
#pragma unroll
        for (int j = 0; j < 4; j++) {
            float2 v = unpack2(acc2[i][j]);
            int col = rn + 2 * j;
            C[(size_t)row * DQ + n0 + col]     = tanhf(v.x + ew[col]);
            C[(size_t)row * DQ + n0 + col + 1] = tanhf(v.y + ew[col + 1]);
        }
    }
}

// ---------------------------------------------------------------------------
// K6a: transpose-to-k-major + bf16 hi/lo split of Wb -> g_WbB_h/l [KTOT][128]
// cols 97..127 zero-padded.
// ---------------------------------------------------------------------------
__global__ void k_wbt(const float* __restrict__ Wb) {
    int idx = blockIdx.x * 256 + threadIdx.x;
    if (idx >= KTOT * 128) return;
    int k = idx >> 7;
    int n = idx & 127;
    float w = (n < CQ) ? Wb[(size_t)k * CQ + n] : 0.f;
    __nv_bfloat16 wh = __float2bfloat16(w);
    float r = w - __bfloat162float(wh);
    g_WbB_h[idx] = wh;
    g_WbB_l[idx] = __float2bfloat16(r);
}

// ---------------------------------------------------------------------------
// K6b: final block-bilinear GEMM on HMMA (mma.sync bf16, 3-split, f32 accum).
// out[n,c] = sum_{kb,i,j} hv[n,kb*64+i]*tv[n,kb*64+j]*Wb[kb*4096+i*64+j, c]
// grid (32 M-tiles, 12 kb), 256 thr = 8 warps; warp w -> rows w*16..w*16+15,
// all 128 cols. Per i-step: A fragment synthesized in registers
// (a[m][j] = hv_i[m]*tv[m][j], bf16 hi/lo), B tile [64 j][128 n] bf16 hi/lo
// double-buffered in SMEM (+pad 8 -> conflict-free ldmatrix.x2.trans).
// SMEM: hv 32KB + 2 stages x (hi+lo) x 64x136 bf16 = 102400 B.
// ---------------------------------------------------------------------------
#define BSTR 136
#define BTILE (64 * BSTR)

__device__ __forceinline__ void load_pf(uint4* pf, int kb, int i, int tid) {
    size_t kbase = ((size_t)kb * 4096 + (size_t)i * 64) * 128;
#pragma unroll
    for (int q = 0; q < 8; q++) {
        int ch = tid + q * 256;            // 0..2047
        int split = ch >> 10;              // 0 = hi, 1 = lo
        int idx = ch & 1023;               // 8-elem chunk within tile
        const __nv_bfloat16* src = (split ? g_WbB_l : g_WbB_h) + kbase + (size_t)idx * 8;
        pf[q] = *(const uint4*)src;
    }
}

__device__ __forceinline__ void store_pf(const uint4* pf, __nv_bfloat16* Bbuf,
                                         int st, int tid) {
#pragma unroll
    for (int q = 0; q < 8; q++) {
        int ch = tid + q * 256;
        int split = ch >> 10;
        int idx = ch & 1023;
        int row = idx >> 4, col8 = idx & 15;
        *(uint4*)(Bbuf + (size_t)(st * 2 + split) * BTILE + row * BSTR + col8 * 8) = pf[q];
    }
}

extern __shared__ char s_hm[];
__global__ __launch_bounds__(256, 1) void gemm_final_hmma() {
    float* hv_s = (float*)s_hm;                          // [128][64]
    __nv_bfloat16* Bbuf = (__nv_bfloat16*)(s_hm + 32768);
    int tid = threadIdx.x, lane = tid & 31, wid = tid >> 5;
    int p0 = blockIdx.x * 128;
    int kb = blockIdx.y;

    // hv tile [row][i]
    for (int t = tid; t < 128 * 64; t += 256) {
        int r = t >> 6, c = t & 63;
        hv_s[t] = g_hv[(size_t)(p0 + r) * DQ + kb * 64 + c];
    }

    // tv values in registers: warp rows rA = wid*16 + lane/4, rB = rA+8
    int rA = wid * 16 + (lane >> 2), rB = rA + 8;
    float tvA[16], tvB[16];
    {
        const float* tA = g_tv + (size_t)(p0 + rA) * DQ + kb * 64;
        const float* tB = g_tv + (size_t)(p0 + rB) * DQ + kb * 64;
#pragma unroll
        for (int c = 0; c < 4; c++) {
            int j0 = c * 16 + (lane & 3) * 2;
            tvA[c * 4 + 0] = tA[j0];     tvA[c * 4 + 1] = tA[j0 + 1];
            tvA[c * 4 + 2] = tA[j0 + 8]; tvA[c * 4 + 3] = tA[j0 + 9];
            tvB[c * 4 + 0] = tB[j0];     tvB[c * 4 + 1] = tB[j0 + 1];
            tvB[c * 4 + 2] = tB[j0 + 8]; tvB[c * 4 + 3] = tB[j0 + 9];
        }
    }

    uint4 pf[8];
    load_pf(pf, kb, 0, tid);
    store_pf(pf, Bbuf, 0, tid);
    __syncthreads();

    float acc[64];
#pragma unroll
    for (int t = 0; t < 64; t++) acc[t] = 0.f;

    for (int i = 0; i < 64; i++) {
        int st = i & 1;
        if (i + 1 < 64) load_pf(pf, kb, i + 1, tid);   // prefetch next tile

        float hA = hv_s[rA * 64 + i];
        float hB = hv_s[rB * 64 + i];

#pragma unroll
        for (int c = 0; c < 4; c++) {
            // ---- synth A fragments (hi/lo split) ----
            float pA0 = hA * tvA[c * 4 + 0], pA1 = hA * tvA[c * 4 + 1];
            float pA2 = hA * tvA[c * 4 + 2], pA3 = hA * tvA[c * 4 + 3];
            float pB0 = hB * tvB[c * 4 + 0], pB1 = hB * tvB[c * 4 + 1];
            float pB2 = hB * tvB[c * 4 + 2], pB3 = hB * tvB[c * 4 + 3];
            uint32_t ah0 = bfpack(pA0, pA1), ah1 = bfpack(pB0, pB1);
            uint32_t ah2 = bfpack(pA2, pA3), ah3 = bfpack(pB2, pB3);
            float rA0 = pA0 - __bfloat162float(__float2bfloat16(pA0));
            float rA1 = pA1 - __bfloat162float(__float2bfloat16(pA1));
            float rA2 = pA2 - __bfloat162float(__float2bfloat16(pA2));
            float rA3 = pA3 - __bfloat162float(__float2bfloat16(pA3));
            float rB0 = pB0 - __bfloat162float(__float2bfloat16(pB0));
            float rB1 = pB1 - __bfloat162float(__float2bfloat16(pB1));
            float rB2 = pB2 - __bfloat162float(__float2bfloat16(pB2));
            float rB3 = pB3 - __bfloat162float(__float2bfloat16(pB3));
            uint32_t al0 = bfpack(rA0, rA1), al1 = bfpack(rB0, rB1);
            uint32_t al2 = bfpack(rA2, rA3), al3 = bfpack(rB2, rB3);

            // ---- B fragment bases for this k-chunk (rows c*16 + 0..15) ----
            int brow = c * 16 + (lane & 15);
            uint32_t base_h = smem_u32(Bbuf + (size_t)(st * 2 + 0) * BTILE + brow * BSTR);
            uint32_t base_l = smem_u32(Bbuf + (size_t)(st * 2 + 1) * BTILE + brow * BSTR);

#pragma unroll
            for (int t = 0; t < 16; t++) {
                uint32_t bh0, bh1, bl0, bl1;
                ldsm2t(bh0, bh1, base_h + t * 16);
                ldsm2t(bl0, bl1, base_l + t * 16);
                mma16816(acc + t * 4, ah0, ah1, ah2, ah3, bh0, bh1);
                mma16816(acc + t * 4, ah0, ah1, ah2, ah3, bl0, bl1);
                mma16816(acc + t * 4, al0, al1, al2, al3, bh0, bh1);
            }
        }
        __syncthreads();
        if (i + 1 < 64) store_pf(pf, Bbuf, st ^ 1, tid);
        __syncthreads();
    }

    // ---- epilogue: write split-K partials ----
    float* P = g_part + (size_t)kb * NP * CQ;
#pragma unroll
    for (int t = 0; t < 16; t++) {
        int col = t * 8 + (lane & 3) * 2;
        if (col < CQ) {
            P[(size_t)(p0 + rA) * CQ + col] = acc[t * 4 + 0];
            P[(size_t)(p0 + rB) * CQ + col] = acc[t * 4 + 2];
            if (col + 1 < CQ) {
                P[(size_t)(p0 + rA) * CQ + col + 1] = acc[t * 4 + 1];
                P[(size_t)(p0 + rB) * CQ + col + 1] = acc[t * 4 + 3];
            }
        }
    }
}

// ---------------------------------------------------------------------------
// K7: deterministic split-K reduction + bias
// ---------------------------------------------------------------------------
__global__ void k_reduce(const float* __restrict__ bbias, float* __restrict__ out) {
    int idx = blockIdx.x * 256 + threadIdx.x;
    if (idx < NP * CQ) {
        int c = idx % CQ;
        float s = bbias[c];
#pragma unroll
        for (int z = 0; z < NKB; z++) s += g_part[(size_t)z * NP * CQ + idx];
        out[idx] = s;
    }
}

// ---------------------------------------------------------------------------
extern "C" void kernel_launch(void* const* d_in, const int* in_sizes, int n_in,
                              void* d_out, int out_size) {
    const float* seq     = (const float*)d_in[0];   // [B,L,H]
    const float* ent_lhs = (const float*)d_in[1];   // [B,M,H]
    const float* attn    = (const float*)d_in[2];   // [B,NH,M,L]
    const int*   labels  = (const int*)d_in[3];     // [B,M]
    const int*   hts     = (const int*)d_in[4];     // [B,R,2]
    const float* Wh      = (const float*)d_in[5];   // [2H,D]
    const float* bh      = (const float*)d_in[6];   // [D]
    const float* Wt      = (const float*)d_in[7];
    const float* bt      = (const float*)d_in[8];
    const float* Wb      = (const float*)d_in[9];   // [D*BLK,C]
    const float* bbias   = (const float*)d_in[10];  // [C]
    float* out = (float*)d_out;

    const int HMMA_SMEM = 32768 + 4 * BTILE * 2;    // 102400 bytes
    cudaFuncSetAttribute(gemm_final_hmma,
                         cudaFuncAttributeMaxDynamicSharedMemorySize, HMMA_SMEM);

    k_build<<<BQ, EQ>>>(labels);
    k_ent_emb<<<NEQ, 256>>>(ent_lhs);
    k_ent_attn<<<dim3(NHQ, NEQ), 128>>>(attn);
    k_ht<<<NP, 128>>>(hts);
    k_wbt<<<(KTOT * 128 + 255) / 256, 256>>>(Wb);
    gemm_rel<<<dim3(HQ / 128, RQ / 128, BQ), 256>>>(seq);
    gemm_ent<<<dim3(DQ / 128, NEQ / 128, 2), 256>>>(Wh, bh, Wt, bt);
    gemm_extract<<<dim3(DQ / 128, NP / 128, 2), 256>>>(hts, Wh, Wt);
    gemm_final_hmma<<<dim3(NP / 128, NKB), 256, HMMA_SMEM>>>();
    k_reduce<<<(NP * CQ + 255) / 256, 256>>>(bbias, out);
}

// round 13
// speedup vs baseline: 3.3481x; 1.3228x over previous
#include <cuda_runtime.h>
#include <cuda_bf16.h>
#include <math.h>
#include <stdint.h>

// Problem constants
#define BQ 4
#define LQ 512
#define HQ 1024
#define MQ 128
#define EQ 64
#define NHQ 16
#define RQ 1024
#define DQ 768
#define BLKQ 64
#define CQ 97
#define NKB 12           // D / BLK  (split-K planes)
#define NP (BQ * RQ)     // 4096 pairs
#define NEQ (BQ * EQ)    // 256 distinct entities
#define KTOT 49152       // D * BLK

// -------- scratch (static device globals: allocation-guard safe) ----------
__device__ float g_ent_emb[NEQ * HQ];              // 1 MB
__device__ int   g_cnt[NEQ];
__device__ int   g_list[NEQ * MQ];
__device__ float g_ent_attn[NEQ * NHQ * LQ];       // 8 MB
__device__ __nv_bfloat16 g_hth[NP * LQ];           // 4 MB  ht hi split
__device__ __nv_bfloat16 g_htl[NP * LQ];           // 4 MB  ht lo split
__device__ __nv_bfloat16 g_seqh[BQ * LQ * HQ];     // 4 MB  seq hi
__device__ __nv_bfloat16 g_seql[BQ * LQ * HQ];     // 4 MB  seq lo
__device__ __nv_bfloat16 g_relh[NP * HQ];          // 8 MB  rel hi
__device__ __nv_bfloat16 g_rell[NP * HQ];          // 8 MB  rel lo
__device__ __nv_bfloat16 g_Wsph[2 * HQ * DQ];      // 3 MB  W bottom-half hi (z-major)
__device__ __nv_bfloat16 g_Wspl[2 * HQ * DQ];      // 3 MB  W bottom-half lo
__device__ float g_hv[NP * DQ];                    // 12 MB
__device__ float g_tv[NP * DQ];                    // 12 MB
__device__ float g_entW[2 * NEQ * DQ];             // 1.5 MB
__device__ float g_part[NKB * NP * CQ];            // 19 MB split-K partials
__device__ __nv_bfloat16 g_WbB_h[KTOT * 128];      // 12.6 MB  Wb k-major hi
__device__ __nv_bfloat16 g_WbB_l[KTOT * 128];      // 12.6 MB  Wb k-major lo

// -------- packed f32x2 helpers (used by gemm_ent) ----
typedef unsigned long long u64t;

__device__ __forceinline__ u64t pack2b(float v) {
    u64t r; asm("mov.b64 %0, {%1, %1};" : "=l"(r) : "f"(v)); return r;
}
__device__ __forceinline__ void fma2(u64t& d, u64t a, u64t b) {
    asm("fma.rn.f32x2 %0, %1, %2, %0;" : "+l"(d) : "l"(a), "l"(b));
}
__device__ __forceinline__ float2 unpack2(u64t v) {
    float2 r; asm("mov.b64 {%0, %1}, %2;" : "=f"(r.x), "=f"(r.y) : "l"(v)); return r;
}

// -------- HMMA helpers ----
__device__ __forceinline__ uint32_t smem_u32(const void* p) {
    return (uint32_t)__cvta_generic_to_shared(p);
}
__device__ __forceinline__ void mma16816(float* d, uint32_t a0, uint32_t a1,
                                         uint32_t a2, uint32_t a3,
                                         uint32_t b0, uint32_t b1) {
    asm volatile(
        "mma.sync.aligned.m16n8k16.row.col.f32.bf16.bf16.f32 "
        "{%0,%1,%2,%3}, {%4,%5,%6,%7}, {%8,%9}, {%0,%1,%2,%3};"
        : "+f"(d[0]), "+f"(d[1]), "+f"(d[2]), "+f"(d[3])
        : "r"(a0), "r"(a1), "r"(a2), "r"(a3), "r"(b0), "r"(b1));
}
__device__ __forceinline__ void ldsm2t(uint32_t& r0, uint32_t& r1, uint32_t addr) {
    asm volatile("ldmatrix.sync.aligned.m8n8.x2.trans.shared.b16 {%0,%1}, [%2];"
                 : "=r"(r0), "=r"(r1) : "r"(addr));
}
__device__ __forceinline__ uint32_t bfpack(float lo, float hi) {
    __nv_bfloat162 t = __floats2bfloat162_rn(lo, hi);
    return *(uint32_t*)&t;
}
__device__ __forceinline__ void split2(float a0, float a1, uint32_t& hp, uint32_t& lp) {
    __nv_bfloat16 h0 = __float2bfloat16(a0), h1 = __float2bfloat16(a1);
    hp = (uint32_t)__bfloat16_as_ushort(h0) | ((uint32_t)__bfloat16_as_ushort(h1) << 16);
    lp = bfpack(a0 - __bfloat162float(h0), a1 - __bfloat162float(h1));
}

extern __shared__ char s_dyn[];

// ---------------------------------------------------------------------------
// K0: per (b,e) mention index lists
// ---------------------------------------------------------------------------
__global__ void k_build(const int* __restrict__ labels) {
    int b = blockIdx.x, e = threadIdx.x;
    int c = 0;
    int* lst = g_list + (b * EQ + e) * MQ;
    for (int m = 0; m < MQ; m++)
        if (labels[b * MQ + m] == e) lst[c++] = m;
    g_cnt[b * EQ + e] = c;
}

// ---------------------------------------------------------------------------
// K1: segment logsumexp over mentions -> ent_emb [B,E,H]
// ---------------------------------------------------------------------------
__global__ void k_ent_emb(const float* __restrict__ ent_lhs) {
    int be = blockIdx.x;
    int b = be / EQ;
    __shared__ int s_list[MQ];
    int cnt = g_cnt[be];
    for (int i = threadIdx.x; i < cnt; i += 256) s_list[i] = g_list[be * MQ + i];
    __syncthreads();
    const float* base = ent_lhs + (size_t)b * MQ * HQ;
    for (int h = threadIdx.x; h < HQ; h += 256) {
        float o = 0.f;
        if (cnt > 0) {
            float mx = -3.4e38f;
            for (int i = 0; i < cnt; i++) mx = fmaxf(mx, base[s_list[i] * HQ + h]);
            float s = 0.f;
            for (int i = 0; i < cnt; i++) s += expf(base[s_list[i] * HQ + h] - mx);
            o = mx + logf(s);
        }
        g_ent_emb[be * HQ + h] = o;
    }
}

// ---------------------------------------------------------------------------
// K2: mean mention attention -> ent_attn [B,E,NH,L]
// ---------------------------------------------------------------------------
__global__ void k_ent_attn(const float* __restrict__ attn) {
    int be = blockIdx.y, nh = blockIdx.x;
    int b = be / EQ;
    int cnt = g_cnt[be];
    __shared__ int s_list[MQ];
    for (int i = threadIdx.x; i < cnt; i += 128) s_list[i] = g_list[be * MQ + i];
    __syncthreads();
    float inv = (cnt > 0) ? 1.f / (float)cnt : 0.f;
    const float* abase = attn + ((size_t)(b * NHQ + nh)) * MQ * LQ;
    float* obase = g_ent_attn + ((size_t)(be * NHQ + nh)) * LQ;
    for (int l = threadIdx.x; l < LQ; l += 128) {
        float s = 0.f;
        for (int i = 0; i < cnt; i++) s += abase[s_list[i] * LQ + l];
        obase[l] = s * inv;
    }
}

// ---------------------------------------------------------------------------
// K3: pair attention product, mean over heads, normalize -> bf16 splits
// ---------------------------------------------------------------------------
__global__ void k_ht(const int* __restrict__ hts) {
    int n = blockIdx.x;
    int b = n / RQ;
    int he = hts[n * 2 + 0];
    int te = hts[n * 2 + 1];
    const float* ha = g_ent_attn + ((size_t)(b * EQ + he)) * NHQ * LQ;
    const float* ta = g_ent_attn + ((size_t)(b * EQ + te)) * NHQ * LQ;
    float v[4];
    float loc = 0.f;
#pragma unroll
    for (int rep = 0; rep < 4; rep++) {
        int l = threadIdx.x + rep * 128;
        float acc = 0.f;
#pragma unroll
        for (int nh = 0; nh < NHQ; nh++) acc += ha[nh * LQ + l] * ta[nh * LQ + l];
        v[rep] = acc * (1.0f / NHQ);
        loc += v[rep];
    }
    __shared__ float red[128];
    red[threadIdx.x] = loc;
    __syncthreads();
    for (int s = 64; s > 0; s >>= 1) {
        if (threadIdx.x < s) red[threadIdx.x] += red[threadIdx.x + s];
        __syncthreads();
    }
    float inv = 1.f / (red[0] + 1e-5f);
#pragma unroll
    for (int rep = 0; rep < 4; rep++) {
        int l = threadIdx.x + rep * 128;
        float val = v[rep] * inv;
        __nv_bfloat16 h = __float2bfloat16(val);
        g_hth[(size_t)n * LQ + l] = h;
        g_htl[(size_t)n * LQ + l] = __float2bfloat16(val - __bfloat162float(h));
    }
}

// ---------------------------------------------------------------------------
// K3b/K3c: bf16 hi/lo splits of seq and W bottom halves
// ---------------------------------------------------------------------------
__global__ void k_seqsplit(const float* __restrict__ seq) {
    int idx = blockIdx.x * 256 + threadIdx.x;
    if (idx >= BQ * LQ * HQ) return;
    float w = seq[idx];
    __nv_bfloat16 h = __float2bfloat16(w);
    g_seqh[idx] = h;
    g_seql[idx] = __float2bfloat16(w - __bfloat162float(h));
}

__global__ void k_wsplit(const float* __restrict__ Wh, const float* __restrict__ Wt) {
    int idx = blockIdx.x * 256 + threadIdx.x;
    if (idx >= 2 * HQ * DQ) return;
    int z = idx / (HQ * DQ);
    int r = idx - z * (HQ * DQ);
    float w = (z ? Wt : Wh)[(size_t)(HQ + r / DQ) * DQ + (r % DQ)];
    __nv_bfloat16 h = __float2bfloat16(w);
    g_Wsph[idx] = h;
    g_Wspl[idx] = __float2bfloat16(w - __bfloat162float(h));
}

// ---------------------------------------------------------------------------
// HMMA GEMM tiles: A [128 rows][32 k] pad-40 bf16 hi/lo, B [32 k][128 n]
// pad-136 bf16 hi/lo, double buffered. 8 warps, each 16 rows x 128 cols.
// ---------------------------------------------------------------------------
#define EA_STR 40
#define EB_STR 136
#define EA_SEG (128 * EA_STR)            // 5120 elems
#define EB_SEG (32 * EB_STR)             // 4352 elems
#define HG_SMEM ((4 * EA_SEG + 4 * EB_SEG) * 2)   // 75776 bytes

__device__ __forceinline__ void hg_load(uint4* pfA, uint4* pfB,
        const __nv_bfloat16* Ah_, const __nv_bfloat16* Al_, int astr,
        const __nv_bfloat16* Bh_, const __nv_bfloat16* Bl_, int bstr,
        int p0, int n0, int ks, int tid) {
#pragma unroll
    for (int q = 0; q < 4; q++) {
        int ch = tid + q * 256;          // 0..1023
        int sp = ch >> 9, idx = ch & 511;
        {
            int row = idx >> 2, c8 = idx & 3;
            const __nv_bfloat16* src = (sp ? Al_ : Ah_) +
                (size_t)(p0 + row) * astr + ks * 32 + c8 * 8;
            pfA[q] = *(const uint4*)src;
        }
        {
            int kr = idx >> 4, c8 = idx & 15;
            const __nv_bfloat16* src = (sp ? Bl_ : Bh_) +
                (size_t)(ks * 32 + kr) * bstr + n0 + c8 * 8;
            pfB[q] = *(const uint4*)src;
        }
    }
}

__device__ __forceinline__ void hg_store(const uint4* pfA, const uint4* pfB,
        __nv_bfloat16* As, __nv_bfloat16* Bs, int st, int tid) {
#pragma unroll
    for (int q = 0; q < 4; q++) {
        int ch = tid + q * 256;
        int sp = ch >> 9, idx = ch & 511;
        {
            int row = idx >> 2, c8 = idx & 3;
            *(uint4*)(As + (st * 2 + sp) * EA_SEG + row * EA_STR + c8 * 8) = pfA[q];
        }
        {
            int kr = idx >> 4, c8 = idx & 15;
            *(uint4*)(Bs + (st * 2 + sp) * EB_SEG + kr * EB_STR + c8 * 8) = pfB[q];
        }
    }
}

__device__ __forceinline__ void hg_compute(float* acc, const __nv_bfloat16* As,
        __nv_bfloat16* Bs, int st, int rA, int rB, int ko, int lane) {
    const __nv_bfloat16* Ah = As + (st * 2 + 0) * EA_SEG;
    const __nv_bfloat16* Al = As + (st * 2 + 1) * EA_SEG;
    uint32_t bh_base = smem_u32(Bs + (st * 2 + 0) * EB_SEG);
    uint32_t bl_base = smem_u32(Bs + (st * 2 + 1) * EB_SEG);
#pragma unroll
    for (int kc = 0; kc < 32; kc += 16) {
        uint32_t ah0 = *(const uint32_t*)(Ah + rA * EA_STR + kc + ko);
        uint32_t ah1 = *(const uint32_t*)(Ah + rB * EA_STR + kc + ko);
        uint32_t ah2 = *(const uint32_t*)(Ah + rA * EA_STR + kc + 8 + ko);
        uint32_t ah3 = *(const uint32_t*)(Ah + rB * EA_STR + kc + 8 + ko);
        uint32_t al0 = *(const uint32_t*)(Al + rA * EA_STR + kc + ko);
        uint32_t al1 = *(const uint32_t*)(Al + rB * EA_STR + kc + ko);
        uint32_t al2 = *(const uint32_t*)(Al + rA * EA_STR + kc + 8 + ko);
        uint32_t al3 = *(const uint32_t*)(Al + rB * EA_STR + kc + 8 + ko);
        uint32_t bh = bh_base + (kc + (lane & 15)) * (EB_STR * 2);
        uint32_t bl = bl_base + (kc + (lane & 15)) * (EB_STR * 2);
#pragma unroll
        for (int t = 0; t < 16; t++) {
            uint32_t b0, b1, c0, c1;
            ldsm2t(b0, b1, bh + t * 16);
            ldsm2t(c0, c1, bl + t * 16);
            mma16816(acc + t * 4, ah0, ah1, ah2, ah3, b0, b1);
            mma16816(acc + t * 4, ah0, ah1, ah2, ah3, c0, c1);
            mma16816(acc + t * 4, al0, al1, al2, al3, b0, b1);
        }
    }
}

// ---------------------------------------------------------------------------
// K4: rel = ht @ seq  (HMMA 3-split)  M=4096 N=1024 K=512, epilogue -> splits
// ---------------------------------------------------------------------------
__global__ __launch_bounds__(256) void gemm_rel_hmma() {
    __nv_bfloat16* As = (__nv_bfloat16*)s_dyn;
    __nv_bfloat16* Bs = (__nv_bfloat16*)s_dyn + 4 * EA_SEG;
    int tid = threadIdx.x, lane = tid & 31, wid = tid >> 5;
    int n0 = blockIdx.x * 128, p0 = blockIdx.y * 128;
    int b = p0 >> 10;
    const __nv_bfloat16* Bh_ = g_seqh + (size_t)b * LQ * HQ;
    const __nv_bfloat16* Bl_ = g_seql + (size_t)b * LQ * HQ;
    // p0 is a global pair row; A rows index g_hth directly (batch-flattened)
    uint4 pfA[4], pfB[4];
    hg_load(pfA, pfB, g_hth, g_htl, LQ, Bh_, Bl_, HQ, p0, n0, 0, tid);
    hg_store(pfA, pfB, As, Bs, 0, tid);
    __syncthreads();

    float acc[64];
#pragma unroll
    for (int t = 0; t < 64; t++) acc[t] = 0.f;
    int rA = wid * 16 + (lane >> 2), rB = rA + 8, ko = (lane & 3) * 2;

    for (int ks = 0; ks < 16; ks++) {
        int st = ks & 1;
        if (ks + 1 < 16)
            hg_load(pfA, pfB, g_hth, g_htl, LQ, Bh_, Bl_, HQ, p0, n0, ks + 1, tid);
        hg_compute(acc, As, Bs, st, rA, rB, ko, lane);
        __syncthreads();
        if (ks + 1 < 16) hg_store(pfA, pfB, As, Bs, st ^ 1, tid);
        __syncthreads();
    }

    int nA = p0 + rA, nB = p0 + rB;
#pragma unroll
    for (int t = 0; t < 16; t++) {
        int col = n0 + t * 8 + (lane & 3) * 2;
        uint32_t hp, lp;
        split2(acc[t * 4 + 0], acc[t * 4 + 1], hp, lp);
        *(uint32_t*)&g_relh[(size_t)nA * HQ + col] = hp;
        *(uint32_t*)&g_rell[(size_t)nA * HQ + col] = lp;
        split2(acc[t * 4 + 2], acc[t * 4 + 3], hp, lp);
        *(uint32_t*)&g_relh[(size_t)nB * HQ + col] = hp;
        *(uint32_t*)&g_rell[(size_t)nB * HQ + col] = lp;
    }
}

// ---------------------------------------------------------------------------
// K5a: entW[z, be, :] = ent_emb[be] @ W_top + bias   (f32x2, tiny)
// ---------------------------------------------------------------------------
__global__ __launch_bounds__(256) void gemm_ent(
    const float* __restrict__ Wh, const float* __restrict__ bh,
    const float* __restrict__ Wt, const float* __restrict__ bt) {
    int z = blockIdx.z;
    int n0 = blockIdx.x * 128;
    int r0 = blockIdx.y * 128;
    const float* W = z ? Wt : Wh;
    const float* bias = z ? bt : bh;

    __shared__ float As[16][128];
    __shared__ float Bsh[16][128];
    int tid = threadIdx.x;
    u64t acc2[8][4];
#pragma unroll
    for (int i = 0; i < 8; i++)
#pragma unroll
        for (int j = 0; j < 4; j++) acc2[i][j] = 0ULL;

    int arow = tid >> 1, akc = (tid & 1) * 8;
    int brow = tid >> 4, bcc = (tid & 15) * 8;
    int rm = (tid >> 4) * 8, rn = (tid & 15) * 8;
    const float* Abase = g_ent_emb + (size_t)r0 * HQ;

    for (int k0 = 0; k0 < HQ; k0 += 16) {
        float4 a0 = *(const float4*)(Abase + (size_t)arow * HQ + k0 + akc);
        float4 a1 = *(const float4*)(Abase + (size_t)arow * HQ + k0 + akc + 4);
        float4 b0 = *(const float4*)(W + (size_t)(k0 + brow) * DQ + n0 + bcc);
        float4 b1 = *(const float4*)(W + (size_t)(k0 + brow) * DQ + n0 + bcc + 4);
        __syncthreads();
        As[akc + 0][arow] = a0.x; As[akc + 1][arow] = a0.y;
        As[akc + 2][arow] = a0.z; As[akc + 3][arow] = a0.w;
        As[akc + 4][arow] = a1.x; As[akc + 5][arow] = a1.y;
        As[akc + 6][arow] = a1.z; As[akc + 7][arow] = a1.w;
        *(float4*)&Bsh[brow][bcc] = b0;
        *(float4*)&Bsh[brow][bcc + 4] = b1;
        __syncthreads();
#pragma unroll
        for (int kk = 0; kk < 16; kk++) {
            float a[8];
            *(float4*)&a[0] = *(const float4*)&As[kk][rm];
            *(float4*)&a[4] = *(const float4*)&As[kk][rm + 4];
            ulonglong2 bu0 = *(const ulonglong2*)&Bsh[kk][rn];
            ulonglong2 bu1 = *(const ulonglong2*)&Bsh[kk][rn + 4];
            u64t b2[4] = {bu0.x, bu0.y, bu1.x, bu1.y};
#pragma unroll
            for (int i = 0; i < 8; i++) {
                u64t a2 = pack2b(a[i]);
#pragma unroll
                for (int j = 0; j < 4; j++) fma2(acc2[i][j], a2, b2[j]);
            }
        }
    }
    float* Cb = g_entW + ((size_t)z * NEQ + r0) * DQ + n0;
#pragma unroll
    for (int i = 0; i < 8; i++)
#pragma unroll
        for (int j = 0; j < 4; j++) {
            float2 v = unpack2(acc2[i][j]);
            int col = rn + 2 * j;
            Cb[(size_t)(rm + i) * DQ + col]     = v.x + bias[n0 + col];
            Cb[(size_t)(rm + i) * DQ + col + 1] = v.y + bias[n0 + col + 1];
        }
}

// ---------------------------------------------------------------------------
// K5b: hv/tv = tanh(rel @ W_bot + gathered entW)  (HMMA 3-split)
// M=4096 N=768 K=1024, z=0/1
// ---------------------------------------------------------------------------
__global__ __launch_bounds__(256) void gemm_extract_hmma(const int* __restrict__ hts) {
    __nv_bfloat16* As = (__nv_bfloat16*)s_dyn;
    __nv_bfloat16* Bs = (__nv_bfloat16*)s_dyn + 4 * EA_SEG;
    int tid = threadIdx.x, lane = tid & 31, wid = tid >> 5;
    int z = blockIdx.z, n0 = blockIdx.x * 128, p0 = blockIdx.y * 128;
    const __nv_bfloat16* Bh_ = g_Wsph + (size_t)z * HQ * DQ;
    const __nv_bfloat16* Bl_ = g_Wspl + (size_t)z * HQ * DQ;

    uint4 pfA[4], pfB[4];
    hg_load(pfA, pfB, g_relh, g_rell, HQ, Bh_, Bl_, DQ, p0, n0, 0, tid);
    hg_store(pfA, pfB, As, Bs, 0, tid);
    __syncthreads();

    float acc[64];
#pragma unroll
    for (int t = 0; t < 64; t++) acc[t] = 0.f;
    int rA = wid * 16 + (lane >> 2), rB = rA + 8, ko = (lane & 3) * 2;

    for (int ks = 0; ks < 32; ks++) {
        int st = ks & 1;
        if (ks + 1 < 32)
            hg_load(pfA, pfB, g_relh, g_rell, HQ, Bh_, Bl_, DQ, p0, n0, ks + 1, tid);
        hg_compute(acc, As, Bs, st, rA, rB, ko, lane);
        __syncthreads();
        if (ks + 1 < 32) hg_store(pfA, pfB, As, Bs, st ^ 1, tid);
        __syncthreads();
    }

    int nA = p0 + rA, nB = p0 + rB;
    int eA = hts[nA * 2 + z], eB = hts[nB * 2 + z];
    const float* ewA = g_entW + ((size_t)z * NEQ + (nA >> 10) * EQ + eA) * DQ + n0;
    const float* ewB = g_entW + ((size_t)z * NEQ + (nB >> 10) * EQ + eB) * DQ + n0;
    float* C = z ? g_tv : g_hv;
#pragma unroll
    for (int t = 0; t < 16; t++) {
        int col = t * 8 + (lane & 3) * 2;
        float2 vA, vB;
        vA.x = tanhf(acc[t * 4 + 0] + ewA[col]);
        vA.y = tanhf(acc[t * 4 + 1] + ewA[col + 1]);
        vB.x = tanhf(acc[t * 4 + 2] + ewB[col]);
        vB.y = tanhf(acc[t * 4 + 3] + ewB[col + 1]);
        *(float2*)&C[(size_t)nA * DQ + n0 + col] = vA;
        *(float2*)&C[(size_t)nB * DQ + n0 + col] = vB;
    }
}

// ---------------------------------------------------------------------------
// K6a: transpose-to-k-major + bf16 hi/lo split of Wb -> g_WbB_h/l [KTOT][128]
// ---------------------------------------------------------------------------
__global__ void k_wbt(const float* __restrict__ Wb) {
    int idx = blockIdx.x * 256 + threadIdx.x;
    if (idx >= KTOT * 128) return;
    int k = idx >> 7;
    int n = idx & 127;
    float w = (n < CQ) ? Wb[(size_t)k * CQ + n] : 0.f;
    __nv_bfloat16 wh = __float2bfloat16(w);
    float r = w - __bfloat162float(wh);
    g_WbB_h[idx] = wh;
    g_WbB_l[idx] = __float2bfloat16(r);
}

// ---------------------------------------------------------------------------
// K6b: final block-bilinear GEMM on HMMA (bf16 3-split, f32 accum).
// ---------------------------------------------------------------------------
#define BSTR 136
#define BTILE (64 * BSTR)

__device__ __forceinline__ void load_pf(uint4* pf, int kb, int i, int tid) {
    size_t kbase = ((size_t)kb * 4096 + (size_t)i * 64) * 128;
#pragma unroll
    for (int q = 0; q < 8; q++) {
        int ch = tid + q * 256;
        int split = ch >> 10;
        int idx = ch & 1023;
        const __nv_bfloat16* src = (split ? g_WbB_l : g_WbB_h) + kbase + (size_t)idx * 8;
        pf[q] = *(const uint4*)src;
    }
}

__device__ __forceinline__ void store_pf(const uint4* pf, __nv_bfloat16* Bbuf,
                                         int st, int tid) {
#pragma unroll
    for (int q = 0; q < 8; q++) {
        int ch = tid + q * 256;
        int split = ch >> 10;
        int idx = ch & 1023;
        int row = idx >> 4, col8 = idx & 15;
        *(uint4*)(Bbuf + (size_t)(st * 2 + split) * BTILE + row * BSTR + col8 * 8) = pf[q];
    }
}

__global__ __launch_bounds__(256, 1) void gemm_final_hmma() {
    float* hv_s = (float*)s_dyn;                          // [128][64]
    __nv_bfloat16* Bbuf = (__nv_bfloat16*)(s_dyn + 32768);
    int tid = threadIdx.x, lane = tid & 31, wid = tid >> 5;
    int p0 = blockIdx.x * 128;
    int kb = blockIdx.y;

    for (int t = tid; t < 128 * 64; t += 256) {
        int r = t >> 6, c = t & 63;
        hv_s[t] = g_hv[(size_t)(p0 + r) * DQ + kb * 64 + c];
    }

    int rA = wid * 16 + (lane >> 2), rB = rA + 8;
    float tvA[16], tvB[16];
    {
        const float* tA = g_tv + (size_t)(p0 + rA) * DQ + kb * 64;
        const float* tB = g_tv + (size_t)(p0 + rB) * DQ + kb * 64;
#pragma unroll
        for (int c = 0; c < 4; c++) {
            int j0 = c * 16 + (lane & 3) * 2;
            tvA[c * 4 + 0] = tA[j0];     tvA[c * 4 + 1] = tA[j0 + 1];
            tvA[c * 4 + 2] = tA[j0 + 8]; tvA[c * 4 + 3] = tA[j0 + 9];
            tvB[c * 4 + 0] = tB[j0];     tvB[c * 4 + 1] = tB[j0 + 1];
            tvB[c * 4 + 2] = tB[j0 + 8]; tvB[c * 4 + 3] = tB[j0 + 9];
        }
    }

    uint4 pf[8];
    load_pf(pf, kb, 0, tid);
    store_pf(pf, Bbuf, 0, tid);
    __syncthreads();

    float acc[64];
#pragma unroll
    for (int t = 0; t < 64; t++) acc[t] = 0.f;

    for (int i = 0; i < 64; i++) {
        int st = i & 1;
        if (i + 1 < 64) load_pf(pf, kb, i + 1, tid);

        float hA = hv_s[rA * 64 + i];
        float hB = hv_s[rB * 64 + i];

#pragma unroll
        for (int c = 0; c < 4; c++) {
            float pA0 = hA * tvA[c * 4 + 0], pA1 = hA * tvA[c * 4 + 1];
            float pA2 = hA * tvA[c * 4 + 2], pA3 = hA * tvA[c * 4 + 3];
            float pB0 = hB * tvB[c * 4 + 0], pB1 = hB * tvB[c * 4 + 1];
            float pB2 = hB * tvB[c * 4 + 2], pB3 = hB * tvB[c * 4 + 3];
            uint32_t ah0 = bfpack(pA0, pA1), ah1 = bfpack(pB0, pB1);
            uint32_t ah2 = bfpack(pA2, pA3), ah3 = bfpack(pB2, pB3);
            float rA0 = pA0 - __bfloat162float(__float2bfloat16(pA0));
            float rA1 = pA1 - __bfloat162float(__float2bfloat16(pA1));
            float rA2 = pA2 - __bfloat162float(__float2bfloat16(pA2));
            float rA3 = pA3 - __bfloat162float(__float2bfloat16(pA3));
            float rB0 = pB0 - __bfloat162float(__float2bfloat16(pB0));
            float rB1 = pB1 - __bfloat162float(__float2bfloat16(pB1));
            float rB2 = pB2 - __bfloat162float(__float2bfloat16(pB2));
            float rB3 = pB3 - __bfloat162float(__float2bfloat16(pB3));
            uint32_t al0 = bfpack(rA0, rA1), al1 = bfpack(rB0, rB1);
            uint32_t al2 = bfpack(rA2, rA3), al3 = bfpack(rB2, rB3);

            int brow = c * 16 + (lane & 15);
            uint32_t base_h = smem_u32(Bbuf + (size_t)(st * 2 + 0) * BTILE + brow * BSTR);
            uint32_t base_l = smem_u32(Bbuf + (size_t)(st * 2 + 1) * BTILE + brow * BSTR);

#pragma unroll
            for (int t = 0; t < 16; t++) {
                uint32_t bh0, bh1, bl0, bl1;
                ldsm2t(bh0, bh1, base_h + t * 16);
                ldsm2t(bl0, bl1, base_l + t * 16);
                mma16816(acc + t * 4, ah0, ah1, ah2, ah3, bh0, bh1);
                mma16816(acc + t * 4, ah0, ah1, ah2, ah3, bl0, bl1);
                mma16816(acc + t * 4, al0, al1, al2, al3, bh0, bh1);
            }
        }
        __syncthreads();
        if (i + 1 < 64) store_pf(pf, Bbuf, st ^ 1, tid);
        __syncthreads();
    }

    float* P = g_part + (size_t)kb * NP * CQ;
#pragma unroll
    for (int t = 0; t < 16; t++) {
        int col = t * 8 + (lane & 3) * 2;
        if (col < CQ) {
            P[(size_t)(p0 + rA) * CQ + col] = acc[t * 4 + 0];
            P[(size_t)(p0 + rB) * CQ + col] = acc[t * 4 + 2];
            if (col + 1 < CQ) {
                P[(size_t)(p0 + rA) * CQ + col + 1] = acc[t * 4 + 1];
                P[(size_t)(p0 + rB) * CQ + col + 1] = acc[t * 4 + 3];
            }
        }
    }
}

// ---------------------------------------------------------------------------
// K7: deterministic split-K reduction + bias
// ---------------------------------------------------------------------------
__global__ void k_reduce(const float* __restrict__ bbias, float* __restrict__ out) {
    int idx = blockIdx.x * 256 + threadIdx.x;
    if (idx < NP * CQ) {
        int c = idx % CQ;
        float s = bbias[c];
#pragma unroll
        for (int z = 0; z < NKB; z++) s += g_part[(size_t)z * NP * CQ + idx];
        out[idx] = s;
    }
}

// ---------------------------------------------------------------------------
extern "C" void kernel_launch(void* const* d_in, const int* in_sizes, int n_in,
                              void* d_out, int out_size) {
    const float* seq     = (const float*)d_in[0];   // [B,L,H]
    const float* ent_lhs = (const float*)d_in[1];   // [B,M,H]
    const float* attn    = (const float*)d_in[2];   // [B,NH,M,L]
    const int*   labels  = (const int*)d_in[3];     // [B,M]
    const int*   hts     = (const int*)d_in[4];     // [B,R,2]
    const float* Wh      = (const float*)d_in[5];   // [2H,D]
    const float* bh      = (const float*)d_in[6];   // [D]
    const float* Wt      = (const float*)d_in[7];
    const float* bt      = (const float*)d_in[8];
    const float* Wb      = (const float*)d_in[9];   // [D*BLK,C]
    const float* bbias   = (const float*)d_in[10];  // [C]
    float* out = (float*)d_out;

    const int FIN_SMEM = 32768 + 4 * BTILE * 2;     // 102400 bytes
    cudaFuncSetAttribute(gemm_final_hmma,
                         cudaFuncAttributeMaxDynamicSharedMemorySize, FIN_SMEM);
    cudaFuncSetAttribute(gemm_rel_hmma,
                         cudaFuncAttributeMaxDynamicSharedMemorySize, HG_SMEM);
    cudaFuncSetAttribute(gemm_extract_hmma,
                         cudaFuncAttributeMaxDynamicSharedMemorySize, HG_SMEM);

    k_build<<<BQ, EQ>>>(labels);
    k_ent_emb<<<NEQ, 256>>>(ent_lhs);
    k_ent_attn<<<dim3(NHQ, NEQ), 128>>>(attn);
    k_ht<<<NP, 128>>>(hts);
    k_seqsplit<<<(BQ * LQ * HQ + 255) / 256, 256>>>(seq);
    k_wsplit<<<(2 * HQ * DQ + 255) / 256, 256>>>(Wh, Wt);
    k_wbt<<<(KTOT * 128 + 255) / 256, 256>>>(Wb);
    gemm_rel_hmma<<<dim3(HQ / 128, NP / 128), 256, HG_SMEM>>>();
    gemm_ent<<<dim3(DQ / 128, NEQ / 128, 2), 256>>>(Wh, bh, Wt, bt);
    gemm_extract_hmma<<<dim3(DQ / 128, NP / 128, 2), 256, HG_SMEM>>>(hts);
    gemm_final_hmma<<<dim3(NP / 128, NKB), 256, FIN_SMEM>>>();
    k_reduce<<<(NP * CQ + 255) / 256, 256>>>(bbias, out);
}